// round 2
// baseline (speedup 1.0000x reference)
#include <cuda_runtime.h>
#include <math.h>

#define BB 32
#define EMB 512
#define DH 1024          // DEC_H = 2*HID
#define LL 64            // MAXLEN
#define VV 32000
#define G4 4096          // 4*DH
#define NBLK_OUT 250     // 32000 / 128

// ---------------- scratch (device globals; no allocation allowed) ----------------
__device__ float g_h[BB * DH];
__device__ float g_c[BB * DH];
__device__ float g_gates[BB * G4];
__device__ float g_ebuf[BB * EMB];
__device__ float g_cat[BB * 2 * DH];      // [e | ctx] for decoder
__device__ float g_inp[BB * DH];
__device__ float g_aw[BB * LL];
__device__ float g_enc_outs[LL * BB * DH];   // 8 MB
__device__ float g_psum[BB * NBLK_OUT];
__device__ float g_pmax[BB * NBLK_OUT];
__device__ int   g_pidx[BB * NBLK_OUT];
__device__ int   g_tok[BB];
__device__ float g_lse[LL * BB];

// ---------------- packed f32x2 helpers (FFMA2: PTX-only on sm_103a) ----------------
__device__ __forceinline__ unsigned long long ffma2(unsigned long long a,
                                                    unsigned long long b,
                                                    unsigned long long c) {
    unsigned long long d;
    asm("fma.rn.f32x2 %0, %1, %2, %3;" : "=l"(d) : "l"(a), "l"(b), "l"(c));
    return d;
}
__device__ __forceinline__ unsigned long long pack2(float lo, float hi) {
    unsigned long long d;
    asm("mov.b64 %0, {%1, %2};" : "=l"(d)
        : "r"(__float_as_uint(lo)), "r"(__float_as_uint(hi)));
    return d;
}
__device__ __forceinline__ void unpack2(unsigned long long v, float& lo, float& hi) {
    unsigned int u0, u1;
    asm("mov.b64 {%0, %1}, %2;" : "=r"(u0), "=r"(u1) : "l"(v));
    lo = __uint_as_float(u0);
    hi = __uint_as_float(u1);
}

__device__ __forceinline__ float sigm(float x) { return 1.f / (1.f + expf(-x)); }

// ---------------- init ----------------
__global__ void k_init(int set_tok) {
    int i = blockIdx.x * blockDim.x + threadIdx.x;
    if (i < BB * DH) { g_h[i] = 0.f; g_c[i] = 0.f; }
    if (set_tok && i < BB) g_tok[i] = 127;
}

// ---------------- gathers ----------------
__global__ void k_enc_gather(const int* __restrict__ x,
                             const float* __restrict__ emb, int t) {
    int b = blockIdx.x, d = threadIdx.x;
    g_ebuf[b * EMB + d] = emb[(long)x[b * LL + t] * EMB + d];
}

__global__ void k_dec_gather(const float* __restrict__ emb) {
    int b = blockIdx.x;
    int tok = g_tok[b];
    for (int d = threadIdx.x; d < DH; d += blockDim.x)
        g_cat[b * 2 * DH + d] = emb[(long)tok * DH + d];
}

// ---------------- generic small-M GEMM: C[r][j] (+)= sum_k A[r][k] W[k][j] (+bias) ----------------
// grid.x * blockDim.x == N ; grid.y covers batch rows in RPB chunks.
template <int RPB>
__global__ void k_gemm(const float* __restrict__ A, int K,
                       const float* __restrict__ W,
                       const float* __restrict__ bias,
                       float* __restrict__ C, int N,
                       int relu, int beta) {
    constexpr int KT = 64;
    constexpr int P = RPB / 2;
    __shared__ __align__(16) float As[KT * RPB];   // [kk][r], r fastest
    const int j = blockIdx.x * blockDim.x + threadIdx.x;
    const int r0 = blockIdx.y * RPB;

    unsigned long long acc[P];
#pragma unroll
    for (int p = 0; p < P; p++) {
        if (beta) acc[p] = pack2(C[(r0 + 2 * p) * N + j], C[(r0 + 2 * p + 1) * N + j]);
        else      acc[p] = 0ull;
    }

    for (int k0 = 0; k0 < K; k0 += KT) {
        for (int i = threadIdx.x; i < KT * RPB; i += blockDim.x) {
            int kk = i / RPB, r = i % RPB;
            As[i] = A[(r0 + r) * K + k0 + kk];
        }
        __syncthreads();
        const unsigned long long* As2 =
            reinterpret_cast<const unsigned long long*>(As);
#pragma unroll 2
        for (int kk = 0; kk < KT; kk++) {
            float w = W[(k0 + kk) * N + j];
            unsigned long long wp = pack2(w, w);
#pragma unroll
            for (int p = 0; p < P; p++)
                acc[p] = ffma2(As2[kk * P + p], wp, acc[p]);
        }
        __syncthreads();
    }

    float bi = bias ? bias[j] : 0.f;
#pragma unroll
    for (int p = 0; p < P; p++) {
        float lo, hi;
        unpack2(acc[p], lo, hi);
        lo += bi; hi += bi;
        if (relu) { lo = fmaxf(lo, 0.f); hi = fmaxf(hi, 0.f); }
        C[(r0 + 2 * p) * N + j] = lo;
        C[(r0 + 2 * p + 1) * N + j] = hi;
    }
}

// ---------------- LSTM cell (i,f,g,o) ----------------
__global__ void k_cell(int t, int store_enc) {
    int b = blockIdx.x, d = threadIdx.x;
    int gi = b * G4 + d;
    float ig = g_gates[gi];
    float fg = g_gates[gi + DH];
    float gg = g_gates[gi + 2 * DH];
    float og = g_gates[gi + 3 * DH];
    int hi_ = b * DH + d;
    float c = g_c[hi_];
    c = sigm(fg) * c + sigm(ig) * tanhf(gg);
    float h = sigm(og) * tanhf(c);
    g_c[hi_] = c;
    g_h[hi_] = h;
    if (store_enc) g_enc_outs[t * BB * DH + hi_] = h;
}

// ---------------- Bahdanau attention weights (softmax over L) ----------------
__global__ void k_attn(const float* __restrict__ attn_w,
                       const float* __restrict__ attn_b) {
    int b = blockIdx.x, l = threadIdx.x;   // 64 threads
    const float* e = g_cat + b * 2 * DH;   // first half holds e
    const float* hb = g_h + b * DH;
    float s = attn_b[l];
    for (int k = 0; k < DH; k++)      s += e[k]  * attn_w[k * LL + l];
    for (int k = 0; k < DH; k++)      s += hb[k] * attn_w[(DH + k) * LL + l];
    __shared__ float sh[LL];
    __shared__ float sh2[LL];
    sh[l] = s;
    __syncthreads();
    float m = -1e30f;
    for (int i = 0; i < LL; i++) m = fmaxf(m, sh[i]);
    float ex = expf(s - m);
    sh2[l] = ex;
    __syncthreads();
    float tot = 0.f;
    for (int i = 0; i < LL; i++) tot += sh2[i];
    g_aw[b * LL + l] = ex / tot;
}

// ---------------- context: ctx[b][d] = sum_l aw[b][l] * enc_outs[l][b][d] ----------------
__global__ void k_ctx() {
    int b = blockIdx.x;
    __shared__ float aws[LL];
    if (threadIdx.x < LL) aws[threadIdx.x] = g_aw[b * LL + threadIdx.x];
    __syncthreads();
    for (int d = threadIdx.x; d < DH; d += blockDim.x) {
        float s = 0.f;
#pragma unroll 8
        for (int l = 0; l < LL; l++)
            s += aws[l] * g_enc_outs[l * BB * DH + b * DH + d];
        g_cat[b * 2 * DH + DH + d] = s;
    }
}

// ---------------- output projection + raw-logit store + partial sumexp/argmax ----------------
__global__ void k_outproj(const float* __restrict__ W,
                          const float* __restrict__ bias,
                          float* __restrict__ out, int t) {
    constexpr int K = DH, KT = 64, P = 16;
    __shared__ __align__(16) float As[KT * BB];
    __shared__ float s_sum[BB][4];
    __shared__ float s_max[BB][4];
    __shared__ int   s_idx[BB][4];
    const int j = blockIdx.x * blockDim.x + threadIdx.x;  // 0..31999

    unsigned long long acc[P];
#pragma unroll
    for (int p = 0; p < P; p++) acc[p] = 0ull;

    for (int k0 = 0; k0 < K; k0 += KT) {
        for (int i = threadIdx.x; i < KT * BB; i += blockDim.x) {
            int kk = i >> 5, r = i & 31;
            As[i] = g_h[r * K + k0 + kk];
        }
        __syncthreads();
        const unsigned long long* As2 =
            reinterpret_cast<const unsigned long long*>(As);
#pragma unroll 2
        for (int kk = 0; kk < KT; kk++) {
            float w = W[(k0 + kk) * VV + j];
            unsigned long long wp = pack2(w, w);
#pragma unroll
            for (int p = 0; p < P; p++)
                acc[p] = ffma2(As2[kk * P + p], wp, acc[p]);
        }
        __syncthreads();
    }

    float bi = bias[j];
    float vals[BB];
#pragma unroll
    for (int p = 0; p < P; p++) {
        float lo, hi;
        unpack2(acc[p], lo, hi);
        vals[2 * p] = lo + bi;
        vals[2 * p + 1] = hi + bi;
    }
#pragma unroll
    for (int b = 0; b < BB; b++)
        out[((long)b * LL + t) * VV + j] = vals[b];   // raw logits; lse subtracted later

    int lane = threadIdx.x & 31, w = threadIdx.x >> 5;
#pragma unroll
    for (int b = 0; b < BB; b++) {
        float v = vals[b];
        float s = expf(v);           // logits are tiny (|v| << 1): no max-shift needed
        float m = v;
        int mi = j;
#pragma unroll
        for (int o = 16; o; o >>= 1) {
            s += __shfl_down_sync(0xffffffffu, s, o);
            float om = __shfl_down_sync(0xffffffffu, m, o);
            int   oi = __shfl_down_sync(0xffffffffu, mi, o);
            if (om > m || (om == m && oi < mi)) { m = om; mi = oi; }
        }
        if (lane == 0) { s_sum[b][w] = s; s_max[b][w] = m; s_idx[b][w] = mi; }
    }
    __syncthreads();
    if (threadIdx.x < BB) {
        int b = threadIdx.x;
        float s = 0.f, m = -1e30f;
        int mi = 0x7fffffff;
#pragma unroll
        for (int q = 0; q < 4; q++) {
            s += s_sum[b][q];
            float om = s_max[b][q];
            int oi = s_idx[b][q];
            if (om > m || (om == m && oi < mi)) { m = om; mi = oi; }
        }
        g_psum[b * NBLK_OUT + blockIdx.x] = s;
        g_pmax[b * NBLK_OUT + blockIdx.x] = m;
        g_pidx[b * NBLK_OUT + blockIdx.x] = mi;
    }
}

// ---------------- per-step lse + greedy token (deterministic fixed-order reduce) ----------------
__global__ void k_reduce(int t) {
    int b = blockIdx.x, tid = threadIdx.x;   // 256 threads
    __shared__ float ss[256];
    __shared__ float sm[256];
    __shared__ int   si[256];
    float s = 0.f, m = -1e30f;
    int mi = 0x7fffffff;
    for (int i = tid; i < NBLK_OUT; i += 256) {
        s += g_psum[b * NBLK_OUT + i];
        float om = g_pmax[b * NBLK_OUT + i];
        int oi = g_pidx[b * NBLK_OUT + i];
        if (om > m || (om == m && oi < mi)) { m = om; mi = oi; }
    }
    ss[tid] = s; sm[tid] = m; si[tid] = mi;
    __syncthreads();
    for (int o = 128; o; o >>= 1) {
        if (tid < o) {
            ss[tid] += ss[tid + o];
            if (sm[tid + o] > sm[tid] ||
                (sm[tid + o] == sm[tid] && si[tid + o] < si[tid])) {
                sm[tid] = sm[tid + o];
                si[tid] = si[tid + o];
            }
        }
        __syncthreads();
    }
    if (tid == 0) {
        g_lse[t * BB + b] = logf(ss[0]);
        g_tok[b] = si[0];
    }
}

// ---------------- final pass: out[b][t][v] -= lse[t][b] ----------------
__global__ void k_finalize(float* __restrict__ out) {
    long idx = (long)blockIdx.x * blockDim.x + threadIdx.x;
    if (idx < (long)BB * LL * VV) {
        long r = idx / VV;
        int t = (int)(r % LL);
        int b = (int)(r / LL);
        out[idx] -= g_lse[t * BB + b];
    }
}

// ---------------- host orchestration ----------------
extern "C" void kernel_launch(void* const* d_in, const int* in_sizes, int n_in,
                              void* d_out, int out_size) {
    const int*   x         = (const int*)  d_in[0];
    const float* enc_embed = (const float*)d_in[1];
    const float* enc_wx    = (const float*)d_in[2];
    const float* enc_wh    = (const float*)d_in[3];
    const float* enc_b     = (const float*)d_in[4];
    const float* dec_embed = (const float*)d_in[5];
    const float* attn_w    = (const float*)d_in[6];
    const float* attn_b    = (const float*)d_in[7];
    const float* comb_w    = (const float*)d_in[8];
    const float* comb_b    = (const float*)d_in[9];
    const float* dec_wx    = (const float*)d_in[10];
    const float* dec_wh    = (const float*)d_in[11];
    const float* dec_b     = (const float*)d_in[12];
    const float* out_w     = (const float*)d_in[13];
    const float* out_b     = (const float*)d_in[14];
    float* out = (float*)d_out;

    float *p_h, *p_ebuf, *p_gates, *p_cat, *p_inp;
    cudaGetSymbolAddress((void**)&p_h, g_h);
    cudaGetSymbolAddress((void**)&p_ebuf, g_ebuf);
    cudaGetSymbolAddress((void**)&p_gates, g_gates);
    cudaGetSymbolAddress((void**)&p_cat, g_cat);
    cudaGetSymbolAddress((void**)&p_inp, g_inp);

    // ---------- encoder ----------
    k_init<<<128, 256>>>(0);
    for (int t = 0; t < LL; t++) {
        k_enc_gather<<<BB, EMB>>>(x, enc_embed, t);
        k_gemm<16><<<dim3(G4 / 128, 2), 128>>>(p_ebuf, EMB, enc_wx, enc_b,
                                               p_gates, G4, 0, 0);
        k_gemm<16><<<dim3(G4 / 128, 2), 128>>>(p_h, DH, enc_wh, nullptr,
                                               p_gates, G4, 0, 1);
        k_cell<<<BB, DH>>>(t, 1);
    }

    // ---------- decoder ----------
    k_init<<<128, 256>>>(1);
    for (int t = 0; t < LL; t++) {
        k_dec_gather<<<BB, 256>>>(dec_embed);
        k_attn<<<BB, LL>>>(attn_w, attn_b);
        k_ctx<<<BB, 256>>>();
        k_gemm<8><<<dim3(DH / 128, 4), 128>>>(p_cat, 2 * DH, comb_w, comb_b,
                                              p_inp, DH, 1, 0);
        k_gemm<16><<<dim3(G4 / 128, 2), 128>>>(p_inp, DH, dec_wx, dec_b,
                                               p_gates, G4, 0, 0);
        k_gemm<16><<<dim3(G4 / 128, 2), 128>>>(p_h, DH, dec_wh, nullptr,
                                               p_gates, G4, 0, 1);
        k_cell<<<BB, DH>>>(t, 0);
        k_outproj<<<NBLK_OUT, 128>>>(out_w, out_b, out, t);
        k_reduce<<<BB, 256>>>(t);
    }

    long total = (long)BB * LL * VV;
    k_finalize<<<(int)((total + 255) / 256), 256>>>(out);
}

// round 3
// speedup vs baseline: 3.9372x; 3.9372x over previous
#include <cuda_runtime.h>
#include <math.h>

#define BB 32
#define EMB 512
#define DH 1024          // DEC_H
#define LL 64            // MAXLEN
#define VV 32000
#define G4 4096          // 4*DH
#define NBLK_OUT 250     // 32000/128
#define KT 128           // staged K chunk
#define SMAXG 8          // max K-split for gates
#define SCOMB 8          // K-split for comb

typedef unsigned long long ull;

// ---------------- scratch ----------------
__device__ float g_h[BB * DH];
__device__ float g_c[BB * DH];
__device__ float g_gp[SMAXG * BB * G4];     // gates partials
__device__ float g_cpp[SCOMB * BB * DH];    // comb partials
__device__ float g_inp[BB * DH];
__device__ float g_cat[BB * 2 * DH];        // [e | ctx]
__device__ float g_enc_outs[LL * BB * DH];  // 8 MB
__device__ float g_psum[BB * NBLK_OUT];
__device__ float g_pmax[BB * NBLK_OUT];
__device__ int   g_pidx[BB * NBLK_OUT];
__device__ int   g_tok[BB];
__device__ float g_lse[LL * BB];

// ---------------- f32x2 helpers ----------------
__device__ __forceinline__ ull ffma2(ull a, ull b, ull c) {
    ull d;
    asm("fma.rn.f32x2 %0, %1, %2, %3;" : "=l"(d) : "l"(a), "l"(b), "l"(c));
    return d;
}
__device__ __forceinline__ ull pack2(float lo, float hi) {
    ull d;
    asm("mov.b64 %0, {%1, %2};" : "=l"(d)
        : "r"(__float_as_uint(lo)), "r"(__float_as_uint(hi)));
    return d;
}
__device__ __forceinline__ void unpack2(ull v, float& lo, float& hi) {
    unsigned int u0, u1;
    asm("mov.b64 {%0, %1}, %2;" : "=r"(u0), "=r"(u1) : "l"(v));
    lo = __uint_as_float(u0); hi = __uint_as_float(u1);
}
__device__ __forceinline__ float sigm(float x) { return 1.f / (1.f + expf(-x)); }

// ---------------- init ----------------
__global__ void k_init(int set_tok) {
    int i = blockIdx.x * blockDim.x + threadIdx.x;
    if (i < BB * DH) { g_h[i] = 0.f; g_c[i] = 0.f; }
    if (set_tok && i < BB) g_tok[i] = 127;
}

// =========================================================================
// Gates GEMM (K-split partials). MODE 0: enc  A=[emb[x[:,t]] | h], K=1536
//                                MODE 1: dec  A=[inp | h],        K=2048
// grid = (32, S) where each y-block handles a 256-wide K slice (2x KT=128).
// block = 128 threads, each thread owns 1 column j, all 32 rows packed.
// =========================================================================
__global__ void k_gates(int mode, const int* __restrict__ x, int t,
                        const float* __restrict__ emb,
                        const float* __restrict__ wx,
                        const float* __restrict__ wh,
                        float* __restrict__ gp) {
    __shared__ __align__(16) float As_lin[32][KT + 1];
    __shared__ __align__(16) ull As2[KT * 16];
    __shared__ int toks[BB];
    const int tid = threadIdx.x;
    const int j = blockIdx.x * 128 + tid;
    const int kbase = blockIdx.y * 256;
    const int bnd = (mode == 0) ? EMB : DH;   // boundary between wx-part and h-part

    if (mode == 0 && tid < BB) toks[tid] = x[tid * LL + t];

    ull acc[16];
#pragma unroll
    for (int p = 0; p < 16; p++) acc[p] = 0ull;

    for (int half = 0; half < 2; half++) {
        const int k0 = kbase + half * KT;
        __syncthreads();
        // phase 1: coalesced global -> linear smem
        for (int i = tid; i < 32 * KT; i += 128) {
            int r = i >> 7, kk = i & (KT - 1);
            int gk = k0 + kk;
            float v;
            if (mode == 0) {
                v = (gk < EMB) ? emb[(long)toks[r] * EMB + gk]
                               : g_h[r * DH + gk - EMB];
            } else {
                v = (gk < DH) ? g_inp[r * DH + gk]
                              : g_h[r * DH + gk - DH];
            }
            As_lin[r][kk] = v;
        }
        __syncthreads();
        // phase 2: transpose-pack into [kk][p] ull layout
        for (int i = tid; i < KT * 16; i += 128) {
            int p = i & 15, kk = i >> 4;
            As2[kk * 16 + p] = pack2(As_lin[2 * p][kk], As_lin[2 * p + 1][kk]);
        }
        __syncthreads();

        const float* W = (k0 < bnd) ? (wx + (size_t)k0 * G4)
                                    : (wh + (size_t)(k0 - bnd) * G4);
        const float* Wp = W + j;
#pragma unroll 1
        for (int kk = 0; kk < KT; kk += 8) {
            float w[8];
#pragma unroll
            for (int u = 0; u < 8; u++) w[u] = __ldg(Wp + (size_t)(kk + u) * G4);
#pragma unroll
            for (int u = 0; u < 8; u++) {
                ull wp = pack2(w[u], w[u]);
                const ull* a = &As2[(kk + u) * 16];
#pragma unroll
                for (int p = 0; p < 16; p++) acc[p] = ffma2(a[p], wp, acc[p]);
            }
        }
    }
    // write partials (no bias): gp[slice][row][j]
    float* o = gp + ((size_t)blockIdx.y * BB) * G4 + j;
#pragma unroll
    for (int p = 0; p < 16; p++) {
        float lo, hi;
        unpack2(acc[p], lo, hi);
        o[(size_t)(2 * p) * G4] = lo;
        o[(size_t)(2 * p + 1) * G4] = hi;
    }
}

// =========================================================================
// comb GEMM: cpp[s] partial of cat(32x2048) @ comb_w(2048x1024)
// grid = (8, 8), block = 128
// =========================================================================
__global__ void k_comb(const float* __restrict__ W_) {
    __shared__ __align__(16) float As_lin[32][KT + 1];
    __shared__ __align__(16) ull As2[KT * 16];
    const int tid = threadIdx.x;
    const int j = blockIdx.x * 128 + tid;
    const int kbase = blockIdx.y * 256;

    ull acc[16];
#pragma unroll
    for (int p = 0; p < 16; p++) acc[p] = 0ull;

    for (int half = 0; half < 2; half++) {
        const int k0 = kbase + half * KT;
        __syncthreads();
        for (int i = tid; i < 32 * KT; i += 128) {
            int r = i >> 7, kk = i & (KT - 1);
            As_lin[r][kk] = g_cat[r * (2 * DH) + k0 + kk];
        }
        __syncthreads();
        for (int i = tid; i < KT * 16; i += 128) {
            int p = i & 15, kk = i >> 4;
            As2[kk * 16 + p] = pack2(As_lin[2 * p][kk], As_lin[2 * p + 1][kk]);
        }
        __syncthreads();
        const float* Wp = W_ + (size_t)k0 * DH + j;
#pragma unroll 1
        for (int kk = 0; kk < KT; kk += 8) {
            float w[8];
#pragma unroll
            for (int u = 0; u < 8; u++) w[u] = __ldg(Wp + (size_t)(kk + u) * DH);
#pragma unroll
            for (int u = 0; u < 8; u++) {
                ull wp = pack2(w[u], w[u]);
                const ull* a = &As2[(kk + u) * 16];
#pragma unroll
                for (int p = 0; p < 16; p++) acc[p] = ffma2(a[p], wp, acc[p]);
            }
        }
    }
    float* o = g_cpp + ((size_t)blockIdx.y * BB) * DH + j;
#pragma unroll
    for (int p = 0; p < 16; p++) {
        float lo, hi;
        unpack2(acc[p], lo, hi);
        o[(size_t)(2 * p) * DH] = lo;
        o[(size_t)(2 * p + 1) * DH] = hi;
    }
}

// comb finalize: inp = relu(bias + sum_s cpp[s])
__global__ void k_combfin(const float* __restrict__ comb_b) {
    int b = blockIdx.x, j = threadIdx.x;
    float s = comb_b[j];
#pragma unroll
    for (int u = 0; u < SCOMB; u++) s += g_cpp[((size_t)u * BB + b) * DH + j];
    g_inp[b * DH + j] = fmaxf(s, 0.f);
}

// =========================================================================
// LSTM cell: gates = bias + sum_s gp[s];  i,f,g,o
// =========================================================================
__global__ void k_cell(const float* __restrict__ bias, int S, int t, int store_enc) {
    int b = blockIdx.x, d = threadIdx.x;
    float ig = bias[d], fg = bias[d + DH], gg = bias[d + 2 * DH], og = bias[d + 3 * DH];
    size_t base = (size_t)b * G4 + d;
    for (int s = 0; s < SMAXG; s++) {
        if (s >= S) break;
        const float* gp = g_gp + (size_t)s * BB * G4 + base;
        ig += gp[0]; fg += gp[DH]; gg += gp[2 * DH]; og += gp[3 * DH];
    }
    int hi_ = b * DH + d;
    float c = g_c[hi_];
    c = sigm(fg) * c + sigm(ig) * tanhf(gg);
    float h = sigm(og) * tanhf(c);
    g_c[hi_] = c;
    g_h[hi_] = h;
    if (store_enc) g_enc_outs[t * BB * DH + hi_] = h;
}

// =========================================================================
// Fused attention: gather e, scores, softmax, context. 1 block per batch row.
// =========================================================================
__global__ void k_attn2(const float* __restrict__ dec_embed,
                        const float* __restrict__ attn_w,
                        const float* __restrict__ attn_b) {
    __shared__ float cat_s[2 * DH];
    __shared__ float sp[4][LL];
    __shared__ float sc[LL];
    __shared__ float exs[LL];
    __shared__ float aw_s[LL];
    const int b = blockIdx.x, tid = threadIdx.x;   // 256 threads
    const int tok = g_tok[b];

    for (int i = tid; i < DH; i += 256) {
        float e = dec_embed[(long)tok * DH + i];
        cat_s[i] = e;
        g_cat[b * 2 * DH + i] = e;      // e half of cat for comb
    }
    for (int i = tid; i < DH; i += 256) cat_s[DH + i] = g_h[b * DH + i];
    __syncthreads();

    // scores: tid = l + 64*kc
    {
        int l = tid & 63, kc = tid >> 6;
        float s = 0.f;
        const float* wp = attn_w + l;
        int kstart = kc * 512;
#pragma unroll 8
        for (int k = 0; k < 512; k++)
            s += cat_s[kstart + k] * wp[(size_t)(kstart + k) * LL];
        sp[kc][l] = s;
    }
    __syncthreads();
    if (tid < LL)
        sc[tid] = attn_b[tid] + sp[0][tid] + sp[1][tid] + sp[2][tid] + sp[3][tid];
    __syncthreads();
    if (tid < LL) {
        float m = -1e30f;
        for (int i = 0; i < LL; i++) m = fmaxf(m, sc[i]);
        exs[tid] = expf(sc[tid] - m);
    }
    __syncthreads();
    if (tid < LL) {
        float tot = 0.f;
        for (int i = 0; i < LL; i++) tot += exs[i];
        aw_s[tid] = exs[tid] / tot;
    }
    __syncthreads();

    // context
    for (int d = tid; d < DH; d += 256) {
        float s = 0.f;
        const float* ep = g_enc_outs + b * DH + d;
#pragma unroll 8
        for (int l = 0; l < LL; l++) s += aw_s[l] * ep[(size_t)l * BB * DH];
        g_cat[b * 2 * DH + DH + d] = s;
    }
}

// =========================================================================
// Output projection (32x32000, K=1024) + raw store + partial sumexp/argmax
// grid = 250, block = 128
// =========================================================================
__global__ void k_outproj(const float* __restrict__ W_,
                          const float* __restrict__ bias,
                          float* __restrict__ out, int t) {
    __shared__ __align__(16) float As_lin[32][KT + 1];
    __shared__ __align__(16) ull As2[KT * 16];
    __shared__ float s_sum[BB][4];
    __shared__ float s_max[BB][4];
    __shared__ int   s_idx[BB][4];
    const int tid = threadIdx.x;
    const int j = blockIdx.x * 128 + tid;

    ull acc[16];
#pragma unroll
    for (int p = 0; p < 16; p++) acc[p] = 0ull;

    for (int k0 = 0; k0 < DH; k0 += KT) {
        __syncthreads();
        for (int i = tid; i < 32 * KT; i += 128) {
            int r = i >> 7, kk = i & (KT - 1);
            As_lin[r][kk] = g_h[r * DH + k0 + kk];
        }
        __syncthreads();
        for (int i = tid; i < KT * 16; i += 128) {
            int p = i & 15, kk = i >> 4;
            As2[kk * 16 + p] = pack2(As_lin[2 * p][kk], As_lin[2 * p + 1][kk]);
        }
        __syncthreads();
        const float* Wp = W_ + (size_t)k0 * VV + j;
#pragma unroll 1
        for (int kk = 0; kk < KT; kk += 8) {
            float w[8];
#pragma unroll
            for (int u = 0; u < 8; u++) w[u] = __ldg(Wp + (size_t)(kk + u) * VV);
#pragma unroll
            for (int u = 0; u < 8; u++) {
                ull wp = pack2(w[u], w[u]);
                const ull* a = &As2[(kk + u) * 16];
#pragma unroll
                for (int p = 0; p < 16; p++) acc[p] = ffma2(a[p], wp, acc[p]);
            }
        }
    }

    float bi = bias[j];
    float vals[BB];
#pragma unroll
    for (int p = 0; p < 16; p++) {
        float lo, hi;
        unpack2(acc[p], lo, hi);
        vals[2 * p] = lo + bi;
        vals[2 * p + 1] = hi + bi;
    }
#pragma unroll
    for (int b = 0; b < BB; b++)
        out[((long)b * LL + t) * VV + j] = vals[b];   // raw logits; lse later

    int lane = tid & 31, w = tid >> 5;
#pragma unroll
    for (int b = 0; b < BB; b++) {
        float v = vals[b];
        float s = expf(v);
        float m = v;
        int mi = j;
#pragma unroll
        for (int o = 16; o; o >>= 1) {
            s += __shfl_down_sync(0xffffffffu, s, o);
            float om = __shfl_down_sync(0xffffffffu, m, o);
            int   oi = __shfl_down_sync(0xffffffffu, mi, o);
            if (om > m || (om == m && oi < mi)) { m = om; mi = oi; }
        }
        if (lane == 0) { s_sum[b][w] = s; s_max[b][w] = m; s_idx[b][w] = mi; }
    }
    __syncthreads();
    if (tid < BB) {
        int b = tid;
        float s = 0.f, m = -1e30f;
        int mi = 0x7fffffff;
#pragma unroll
        for (int q = 0; q < 4; q++) {
            s += s_sum[b][q];
            float om = s_max[b][q]; int oi = s_idx[b][q];
            if (om > m || (om == m && oi < mi)) { m = om; mi = oi; }
        }
        g_psum[b * NBLK_OUT + blockIdx.x] = s;
        g_pmax[b * NBLK_OUT + blockIdx.x] = m;
        g_pidx[b * NBLK_OUT + blockIdx.x] = mi;
    }
}

// ---------------- per-step lse + greedy token ----------------
__global__ void k_reduce(int t) {
    int b = blockIdx.x, tid = threadIdx.x;   // 256 threads
    __shared__ float ss[256];
    __shared__ float sm[256];
    __shared__ int   si[256];
    float s = 0.f, m = -1e30f;
    int mi = 0x7fffffff;
    for (int i = tid; i < NBLK_OUT; i += 256) {
        s += g_psum[b * NBLK_OUT + i];
        float om = g_pmax[b * NBLK_OUT + i];
        int oi = g_pidx[b * NBLK_OUT + i];
        if (om > m || (om == m && oi < mi)) { m = om; mi = oi; }
    }
    ss[tid] = s; sm[tid] = m; si[tid] = mi;
    __syncthreads();
    for (int o = 128; o; o >>= 1) {
        if (tid < o) {
            ss[tid] += ss[tid + o];
            if (sm[tid + o] > sm[tid] ||
                (sm[tid + o] == sm[tid] && si[tid + o] < si[tid])) {
                sm[tid] = sm[tid + o];
                si[tid] = si[tid + o];
            }
        }
        __syncthreads();
    }
    if (tid == 0) {
        g_lse[t * BB + b] = logf(ss[0]);
        g_tok[b] = si[0];
    }
}

// ---------------- final pass: out -= lse ----------------
__global__ void k_finalize(float* __restrict__ out) {
    long idx = (long)blockIdx.x * blockDim.x + threadIdx.x;
    if (idx < (long)BB * LL * VV) {
        long r = idx / VV;
        int t = (int)(r % LL);
        int b = (int)(r / LL);
        out[idx] -= g_lse[t * BB + b];
    }
}

// ---------------- host orchestration ----------------
extern "C" void kernel_launch(void* const* d_in, const int* in_sizes, int n_in,
                              void* d_out, int out_size) {
    const int*   x         = (const int*)  d_in[0];
    const float* enc_embed = (const float*)d_in[1];
    const float* enc_wx    = (const float*)d_in[2];
    const float* enc_wh    = (const float*)d_in[3];
    const float* enc_b     = (const float*)d_in[4];
    const float* dec_embed = (const float*)d_in[5];
    const float* attn_w    = (const float*)d_in[6];
    const float* attn_b    = (const float*)d_in[7];
    const float* comb_w    = (const float*)d_in[8];
    const float* comb_b    = (const float*)d_in[9];
    const float* dec_wx    = (const float*)d_in[10];
    const float* dec_wh    = (const float*)d_in[11];
    const float* dec_b     = (const float*)d_in[12];
    const float* out_w     = (const float*)d_in[13];
    const float* out_b     = (const float*)d_in[14];
    float* out = (float*)d_out;

    float* p_gp;
    cudaGetSymbolAddress((void**)&p_gp, g_gp);

    // ---------- encoder: 6 K-slices (2 emb + 4 h) ----------
    k_init<<<128, 256>>>(0);
    for (int t = 0; t < LL; t++) {
        k_gates<<<dim3(32, 6), 128>>>(0, x, t, enc_embed, enc_wx, enc_wh, p_gp);
        k_cell<<<BB, DH>>>(enc_b, 6, t, 1);
    }

    // ---------- decoder: 8 K-slices (4 inp + 4 h) ----------
    k_init<<<128, 256>>>(1);
    for (int t = 0; t < LL; t++) {
        k_attn2<<<BB, 256>>>(dec_embed, attn_w, attn_b);
        k_comb<<<dim3(8, SCOMB), 128>>>(comb_w);
        k_combfin<<<BB, DH>>>(comb_b);
        k_gates<<<dim3(32, 8), 128>>>(1, x, t, nullptr, dec_wx, dec_wh, p_gp);
        k_cell<<<BB, DH>>>(dec_b, 8, t, 0);
        k_outproj<<<NBLK_OUT, 128>>>(out_w, out_b, out, t);
        k_reduce<<<BB, 256>>>(t);
    }

    long total = (long)BB * LL * VV;
    k_finalize<<<(int)((total + 255) / 256), 256>>>(out);
}

// round 4
// speedup vs baseline: 9.8681x; 2.5064x over previous
#include <cuda_runtime.h>
#include <cuda_bf16.h>
#include <math.h>

#define BB 32
#define EMB 512
#define DH 1024
#define LL 64
#define VV 32000
#define G4 4096

// ---------------- bf16 fragment weight arrays (filled by prep each launch) ----------------
__device__ uint2 Bout[(size_t)4000 * 64 * 32];   // out_w   [nt=4000][kt=64][lane]
__device__ uint2 Bdec[(size_t)512 * 128 * 32];   // dec_wx|dec_wh
__device__ uint2 Benc[(size_t)512 * 96 * 32];    // enc_wx|enc_wh
__device__ uint2 Bcomb[(size_t)128 * 128 * 32];  // comb_w
__device__ uint2 Battn[(size_t)8 * 128 * 32];    // attn_w

// ---------------- state / partials ----------------
__device__ float g_h[BB * DH];
__device__ float g_c[BB * DH];
__device__ float g_inp[BB * DH];
__device__ float g_ctx[BB * DH];
__device__ float g_enc_outs[LL * BB * DH];   // 8 MB
__device__ float g_gp[8 * BB * G4];          // gates partials
__device__ float g_cpp[8 * BB * DH];         // comb partials
__device__ float g_sp[4 * BB * LL];          // score partials
__device__ float g_lg[2 * BB * VV];          // logit partials (k-split 2)
__device__ int   g_tok[BB];
__device__ float g_lse[LL * BB];

// ---------------- helpers ----------------
__device__ __forceinline__ unsigned packbf(float x, float y) {
    unsigned lo = __bfloat16_as_ushort(__float2bfloat16_rn(x));
    unsigned hi = __bfloat16_as_ushort(__float2bfloat16_rn(y));
    return lo | (hi << 16);
}
__device__ __forceinline__ void mma16816(float* c, uint4 a, uint2 b) {
    asm volatile(
        "mma.sync.aligned.m16n8k16.row.col.f32.bf16.bf16.f32 "
        "{%0,%1,%2,%3}, {%4,%5,%6,%7}, {%8,%9}, {%0,%1,%2,%3};"
        : "+f"(c[0]), "+f"(c[1]), "+f"(c[2]), "+f"(c[3])
        : "r"(a.x), "r"(a.y), "r"(a.z), "r"(a.w), "r"(b.x), "r"(b.y));
}
__device__ __forceinline__ float sigm(float x) { return 1.f / (1.f + expf(-x)); }

// ---------------- init ----------------
__global__ void k_init(int set_tok) {
    int i = blockIdx.x * blockDim.x + threadIdx.x;
    if (i < BB * DH) { g_h[i] = 0.f; g_c[i] = 0.f; }
    if (set_tok && i < BB) g_tok[i] = 127;
}

// ---------------- B-fragment prep: W[k][n] f32 -> [nt][kt][lane] uint2 bf16 ----------------
__global__ void k_prepB(const float* __restrict__ W0, const float* __restrict__ W1,
                        int kbnd, int N, int KTOT, int NT, uint2* __restrict__ dst) {
    size_t idx = (size_t)blockIdx.x * blockDim.x + threadIdx.x;
    size_t total = (size_t)NT * KTOT * 32;
    if (idx >= total) return;
    int lane = (int)(idx & 31);
    int kt = (int)((idx >> 5) % KTOT);
    int nt = (int)(idx / ((size_t)KTOT * 32));
    int g = lane >> 2, tg = lane & 3;
    int n = nt * 8 + g;
    int kb = kt * 16 + tg * 2;
    float w[4];
#pragma unroll
    for (int u = 0; u < 4; u++) {
        int k = kb + ((u >> 1) << 3) + (u & 1);
        w[u] = (k < kbnd) ? W0[(size_t)k * N + n] : W1[(size_t)(k - kbnd) * N + n];
    }
    dst[idx] = make_uint2(packbf(w[0], w[1]), packbf(w[2], w[3]));
}

// =========================================================================
// Generic bf16 mma GEMM: Cpart[slice][32][N] = A(32 x K_slice) @ W
// A two-part: cols < bnd from srcA0 (stride bnd; optionally embedding gather
// via tokptr), else srcA1 (stride DH). Block = 128 threads = 4 warps.
// Warp covers NTW n-tiles; block covers 4*NTW*8 columns; grid.y = K slices.
// =========================================================================
template <int KTS, int NTW>
__global__ void __launch_bounds__(128) k_mma(
    const uint2* __restrict__ Bfrag, int KT_total,
    const float* __restrict__ srcA0, const float* __restrict__ srcA1,
    int bnd, int gather, const int* __restrict__ tokptr, int tokstride,
    float* __restrict__ Cpart, int N)
{
    __shared__ unsigned Af[KTS * 256];
    __shared__ int toks[32];
    const int tid = threadIdx.x;
    const int lane = tid & 31, warp = tid >> 5;
    const int kt0 = blockIdx.y * KTS;
    const int c0 = kt0 * 16;

    if (tid < 32) toks[tid] = gather ? tokptr[tid * tokstride] : 0;
    __syncthreads();

    // stage A in per-lane fragment layout (bf16 pairs)
    for (int i = tid; i < KTS * 256; i += 128) {
        int r = i & 3, ln = (i >> 2) & 31, mt = (i >> 7) & 1, kt = i >> 8;
        int g = ln >> 2, tg = ln & 3;
        int row = mt * 16 + g + ((r & 1) << 3);
        int colG = c0 + kt * 16 + tg * 2 + ((r >> 1) << 3);
        float2 v;
        if (colG < bnd) {
            const float* base = gather
                ? srcA0 + (size_t)toks[row] * bnd + colG
                : srcA0 + (size_t)row * bnd + colG;
            v = *reinterpret_cast<const float2*>(base);
        } else {
            v = *reinterpret_cast<const float2*>(srcA1 + (size_t)row * DH + (colG - bnd));
        }
        Af[i] = packbf(v.x, v.y);
    }
    __syncthreads();

    const int ntbase = (blockIdx.x * 4 + warp) * NTW;
    float acc[NTW][2][4];
#pragma unroll
    for (int q = 0; q < NTW; q++)
#pragma unroll
        for (int mt = 0; mt < 2; mt++)
#pragma unroll
            for (int u = 0; u < 4; u++) acc[q][mt][u] = 0.f;

    const uint2* Bp = Bfrag + ((size_t)ntbase * KT_total + kt0) * 32 + lane;
    uint2 bcur[NTW], bnxt[NTW];
#pragma unroll
    for (int q = 0; q < NTW; q++) bcur[q] = Bp[(size_t)q * KT_total * 32];

    for (int kt = 0; kt < KTS; kt++) {
        if (kt + 1 < KTS) {
#pragma unroll
            for (int q = 0; q < NTW; q++)
                bnxt[q] = Bp[((size_t)q * KT_total + kt + 1) * 32];
        }
        uint4 A0 = *reinterpret_cast<const uint4*>(&Af[(kt * 2 + 0) * 128 + lane * 4]);
        uint4 A1 = *reinterpret_cast<const uint4*>(&Af[(kt * 2 + 1) * 128 + lane * 4]);
#pragma unroll
        for (int q = 0; q < NTW; q++) {
            mma16816(acc[q][0], A0, bcur[q]);
            mma16816(acc[q][1], A1, bcur[q]);
        }
#pragma unroll
        for (int q = 0; q < NTW; q++) bcur[q] = bnxt[q];
    }

    // write partials (f32)
    float* Co = Cpart + (size_t)blockIdx.y * BB * N;
    int g = lane >> 2, tg = lane & 3;
#pragma unroll
    for (int q = 0; q < NTW; q++) {
        int ncol = (ntbase + q) * 8 + tg * 2;
#pragma unroll
        for (int mt = 0; mt < 2; mt++) {
            int row = mt * 16 + g;
            *reinterpret_cast<float2*>(Co + (size_t)row * N + ncol) =
                make_float2(acc[q][mt][0], acc[q][mt][1]);
            *reinterpret_cast<float2*>(Co + (size_t)(row + 8) * N + ncol) =
                make_float2(acc[q][mt][2], acc[q][mt][3]);
        }
    }
}

// ---------------- LSTM cell: gates = bias + sum_s gp[s] ----------------
__global__ void k_cell(const float* __restrict__ bias, int S, int t, int store_enc) {
    int b = blockIdx.x, d = threadIdx.x;
    float ig = bias[d], fg = bias[d + DH], gg = bias[d + 2 * DH], og = bias[d + 3 * DH];
    size_t base = (size_t)b * G4 + d;
    for (int s = 0; s < S; s++) {
        const float* gp = g_gp + (size_t)s * BB * G4 + base;
        ig += gp[0]; fg += gp[DH]; gg += gp[2 * DH]; og += gp[3 * DH];
    }
    int hi_ = b * DH + d;
    float c = g_c[hi_];
    c = sigm(fg) * c + sigm(ig) * tanhf(gg);
    float h = sigm(og) * tanhf(c);
    g_c[hi_] = c;
    g_h[hi_] = h;
    if (store_enc) g_enc_outs[t * BB * DH + hi_] = h;
}

// ---------------- softmax over scores + context ----------------
__global__ void k_softmax_ctx(const float* __restrict__ attn_b) {
    __shared__ float sc[LL], exs[LL], aw[LL];
    int b = blockIdx.x, tid = threadIdx.x;   // 256 threads
    if (tid < LL) {
        float s = attn_b[tid];
#pragma unroll
        for (int q = 0; q < 4; q++) s += g_sp[(q * BB + b) * LL + tid];
        sc[tid] = s;
    }
    __syncthreads();
    if (tid < LL) {
        float m = -1e30f;
        for (int i = 0; i < LL; i++) m = fmaxf(m, sc[i]);
        exs[tid] = expf(sc[tid] - m);
    }
    __syncthreads();
    if (tid < LL) {
        float tot = 0.f;
        for (int i = 0; i < LL; i++) tot += exs[i];
        aw[tid] = exs[tid] / tot;
    }
    __syncthreads();
    for (int d = tid; d < DH; d += 256) {
        float s = 0.f;
        const float* ep = g_enc_outs + b * DH + d;
#pragma unroll 8
        for (int l = 0; l < LL; l++) s += aw[l] * ep[(size_t)l * BB * DH];
        g_ctx[b * DH + d] = s;
    }
}

// ---------------- comb finalize: inp = relu(bias + sum partials) ----------------
__global__ void k_combfin(const float* __restrict__ comb_b) {
    int b = blockIdx.x, j = threadIdx.x;
    float s = comb_b[j];
#pragma unroll
    for (int u = 0; u < 8; u++) s += g_cpp[((size_t)u * BB + b) * DH + j];
    g_inp[b * DH + j] = fmaxf(s, 0.f);
}

// ---------------- logits: sum 2 partials + bias, store raw, lse + argmax ----------------
__global__ void k_reduce2(const float* __restrict__ out_b, float* __restrict__ out, int t) {
    __shared__ float ss[256], sm[256];
    __shared__ int   si[256];
    int b = blockIdx.x, tid = threadIdx.x;
    float s = 0.f, m = -1e30f;
    int mi = 0x7fffffff;
    for (int v = tid; v < VV; v += 256) {
        float lg = g_lg[(size_t)b * VV + v] + g_lg[(size_t)(BB + b) * VV + v] + out_b[v];
        out[((size_t)b * LL + t) * VV + v] = lg;
        s += expf(lg);
        if (lg > m) { m = lg; mi = v; }
    }
    ss[tid] = s; sm[tid] = m; si[tid] = mi;
    __syncthreads();
    for (int o = 128; o; o >>= 1) {
        if (tid < o) {
            ss[tid] += ss[tid + o];
            if (sm[tid + o] > sm[tid] ||
                (sm[tid + o] == sm[tid] && si[tid + o] < si[tid])) {
                sm[tid] = sm[tid + o];
                si[tid] = si[tid + o];
            }
        }
        __syncthreads();
    }
    if (tid == 0) {
        g_lse[t * BB + b] = logf(ss[0]);
        g_tok[b] = si[0];
    }
}

// ---------------- final pass: out -= lse ----------------
__global__ void k_finalize(float* __restrict__ out) {
    long idx = (long)blockIdx.x * blockDim.x + threadIdx.x;
    if (idx < (long)BB * LL * VV) {
        long r = idx / VV;
        int t = (int)(r % LL);
        int b = (int)(r / LL);
        out[idx] -= g_lse[t * BB + b];
    }
}

// ---------------- host orchestration ----------------
extern "C" void kernel_launch(void* const* d_in, const int* in_sizes, int n_in,
                              void* d_out, int out_size) {
    const int*   x         = (const int*)  d_in[0];
    const float* enc_embed = (const float*)d_in[1];
    const float* enc_wx    = (const float*)d_in[2];
    const float* enc_wh    = (const float*)d_in[3];
    const float* enc_b     = (const float*)d_in[4];
    const float* dec_embed = (const float*)d_in[5];
    const float* attn_w    = (const float*)d_in[6];
    const float* attn_b    = (const float*)d_in[7];
    const float* comb_w    = (const float*)d_in[8];
    const float* comb_b    = (const float*)d_in[9];
    const float* dec_wx    = (const float*)d_in[10];
    const float* dec_wh    = (const float*)d_in[11];
    const float* dec_b     = (const float*)d_in[12];
    const float* out_w     = (const float*)d_in[13];
    const float* out_b     = (const float*)d_in[14];
    float* out = (float*)d_out;

    uint2 *pBout, *pBdec, *pBenc, *pBcomb, *pBattn;
    float *p_h, *p_inp, *p_ctx, *p_gp, *p_cpp, *p_sp, *p_lg;
    int* p_tok;
    cudaGetSymbolAddress((void**)&pBout, Bout);
    cudaGetSymbolAddress((void**)&pBdec, Bdec);
    cudaGetSymbolAddress((void**)&pBenc, Benc);
    cudaGetSymbolAddress((void**)&pBcomb, Bcomb);
    cudaGetSymbolAddress((void**)&pBattn, Battn);
    cudaGetSymbolAddress((void**)&p_h, g_h);
    cudaGetSymbolAddress((void**)&p_inp, g_inp);
    cudaGetSymbolAddress((void**)&p_ctx, g_ctx);
    cudaGetSymbolAddress((void**)&p_gp, g_gp);
    cudaGetSymbolAddress((void**)&p_cpp, g_cpp);
    cudaGetSymbolAddress((void**)&p_sp, g_sp);
    cudaGetSymbolAddress((void**)&p_lg, g_lg);
    cudaGetSymbolAddress((void**)&p_tok, g_tok);

    // ---------- weight prep (bf16 fragment layout) ----------
    k_prepB<<<32768, 256>>>(out_w, out_w, 1024, VV, 64, 4000, pBout);
    k_prepB<<<8192, 256>>>(dec_wx, dec_wh, 1024, G4, 128, 512, pBdec);
    k_prepB<<<6144, 256>>>(enc_wx, enc_wh, 512, G4, 96, 512, pBenc);
    k_prepB<<<2048, 256>>>(comb_w, comb_w, 2048, DH, 128, 128, pBcomb);
    k_prepB<<<128, 256>>>(attn_w, attn_w, 2048, LL, 128, 8, pBattn);

    // ---------- encoder ----------
    k_init<<<128, 256>>>(0);
    for (int t = 0; t < LL; t++) {
        k_mma<16, 8><<<dim3(16, 6), 128>>>(pBenc, 96, enc_embed, p_h,
                                           512, 1, x + t, LL, p_gp, G4);
        k_cell<<<BB, DH>>>(enc_b, 6, t, 1);
    }

    // ---------- decoder ----------
    k_init<<<128, 256>>>(1);
    for (int t = 0; t < LL; t++) {
        k_mma<32, 2><<<dim3(1, 4), 128>>>(pBattn, 128, dec_embed, p_h,
                                          1024, 1, p_tok, 1, p_sp, LL);
        k_softmax_ctx<<<BB, 256>>>(attn_b);
        k_mma<16, 8><<<dim3(4, 8), 128>>>(pBcomb, 128, dec_embed, p_ctx,
                                          1024, 1, p_tok, 1, p_cpp, DH);
        k_combfin<<<BB, DH>>>(comb_b);
        k_mma<16, 8><<<dim3(16, 8), 128>>>(pBdec, 128, p_inp, p_h,
                                           1024, 0, p_tok, 1, p_gp, G4);
        k_cell<<<BB, DH>>>(dec_b, 8, t, 0);
        k_mma<32, 8><<<dim3(125, 2), 128>>>(pBout, 64, p_h, p_h,
                                            1024, 0, p_tok, 1, p_lg, VV);
        k_reduce2<<<BB, 256>>>(out_b, out, t);
    }

    long total = (long)BB * LL * VV;
    k_finalize<<<(int)((total + 255) / 256), 256>>>(out);
}

// round 5
// speedup vs baseline: 9.9970x; 1.0131x over previous
#include <cuda_runtime.h>
#include <cuda_bf16.h>
#include <math.h>

#define BB 32
#define EMB 512
#define DH 1024
#define LL 64
#define VV 32000
#define G4 4096
#define NPO 125          // outproj n-groups (256 cols each)

typedef unsigned long long ull;

// ---------------- bf16 fragment weight arrays ----------------
__device__ uint2 Bout[(size_t)4000 * 64 * 32];   // out_w   [nt][kt][lane]
__device__ uint2 Bdec[(size_t)512 * 128 * 32];   // dec_wx|dec_wh (gate-permuted cols)
__device__ uint2 Benc[(size_t)512 * 96 * 32];    // enc_wx|enc_wh (gate-permuted cols)
__device__ uint2 Bcomb[(size_t)128 * 128 * 32];  // comb_w

// ---------------- state / partials ----------------
__device__ float g_h[BB * DH];
__device__ float g_c[BB * DH];
__device__ float g_inp[BB * DH];
__device__ float g_ctx[BB * DH];
__device__ float g_enc_outs[LL * BB * DH];
__device__ float g_gp[8 * BB * G4];          // gates partials (permuted cols)
__device__ float g_cpp[8 * BB * DH];         // comb partials
__device__ float g_lg[2 * BB * VV];          // logit partials
__device__ float g_psum[BB * NPO];
__device__ float g_pmax[BB * NPO];
__device__ int   g_pidx[BB * NPO];
__device__ int   g_tok[BB];
__device__ float g_lse[LL * BB];
// arrival counters (one slot per step per group; zeroed once per replay)
__device__ int g_cnt_enc[LL * 32];
__device__ int g_cnt_dec[LL * 32];
__device__ int g_cnt_comb[LL * 8];
__device__ int g_cnt_out[LL * NPO];

// ---------------- helpers ----------------
__device__ __forceinline__ unsigned packbf(float x, float y) {
    unsigned lo = __bfloat16_as_ushort(__float2bfloat16_rn(x));
    unsigned hi = __bfloat16_as_ushort(__float2bfloat16_rn(y));
    return lo | (hi << 16);
}
__device__ __forceinline__ void mma16816(float* c, uint4 a, uint2 b) {
    asm volatile(
        "mma.sync.aligned.m16n8k16.row.col.f32.bf16.bf16.f32 "
        "{%0,%1,%2,%3}, {%4,%5,%6,%7}, {%8,%9}, {%0,%1,%2,%3};"
        : "+f"(c[0]), "+f"(c[1]), "+f"(c[2]), "+f"(c[3])
        : "r"(a.x), "r"(a.y), "r"(a.z), "r"(a.w), "r"(b.x), "r"(b.y));
}
__device__ __forceinline__ float sigm(float x) { return 1.f / (1.f + expf(-x)); }

// ---------------- init ----------------
__global__ void k_init(int phase) {
    int i = blockIdx.x * blockDim.x + threadIdx.x;
    if (i < BB * DH) { g_h[i] = 0.f; g_c[i] = 0.f; }
    if (phase == 0) {
        if (i < LL * 32) { g_cnt_enc[i] = 0; g_cnt_dec[i] = 0; }
        if (i < LL * 8)  g_cnt_comb[i] = 0;
        if (i < LL * NPO) g_cnt_out[i] = 0;
    } else {
        if (i < BB) g_tok[i] = 127;
    }
}

// ---------------- B prep: W[k][n] f32 -> [nt][kt][lane] bf16 frags ----------------
// perm==1: gate-permute columns: n' -> orig_n = gate*DH + p*32 + u
__global__ void k_prepB(const float* __restrict__ W0, const float* __restrict__ W1,
                        int kbnd, int N, int KTOT, int NT, int perm,
                        uint2* __restrict__ dst) {
    size_t idx = (size_t)blockIdx.x * blockDim.x + threadIdx.x;
    size_t total = (size_t)NT * KTOT * 32;
    if (idx >= total) return;
    int lane = (int)(idx & 31);
    int kt = (int)((idx >> 5) % KTOT);
    int nt = (int)(idx / ((size_t)KTOT * 32));
    int g = lane >> 2, tg = lane & 3;
    int n = nt * 8 + g;
    if (perm) {
        int p = n >> 7, r = n & 127, gate = r >> 5, u = r & 31;
        n = gate * DH + (p << 5) + u;
    }
    int kb = kt * 16 + tg * 2;
    float w[4];
#pragma unroll
    for (int u = 0; u < 4; u++) {
        int k = kb + ((u >> 1) << 3) + (u & 1);
        w[u] = (k < kbnd) ? W0[(size_t)k * N + n] : W1[(size_t)(k - kbnd) * N + n];
    }
    dst[idx] = make_uint2(packbf(w[0], w[1]), packbf(w[2], w[3]));
}

// =========================================================================
// Shared mma body macro pieces used by the three GEMM kernels.
// Block = 128 threads (4 warps). Warp covers NTW n-tiles of 8 cols.
// =========================================================================
#define MMA_STAGE_A(KTS)                                                       \
    for (int i = tid; i < (KTS) * 256; i += 128) {                             \
        int r = i & 3, ln = (i >> 2) & 31, mt = (i >> 7) & 1, kt = i >> 8;     \
        int gg_ = ln >> 2, tg_ = ln & 3;                                       \
        int row = mt * 16 + gg_ + ((r & 1) << 3);                              \
        int colG = c0 + kt * 16 + tg_ * 2 + ((r >> 1) << 3);                   \
        float2 v;                                                              \
        if (colG < bnd) {                                                      \
            const float* base = gather                                         \
                ? srcA0 + (size_t)toks[row] * bnd + colG                       \
                : srcA0 + (size_t)row * bnd + colG;                            \
            v = *reinterpret_cast<const float2*>(base);                        \
        } else {                                                               \
            v = *reinterpret_cast<const float2*>(                              \
                srcA1 + (size_t)row * DH + (colG - bnd));                      \
        }                                                                      \
        Af[i] = packbf(v.x, v.y);                                              \
    }

#define MMA_MAIN(KTS, NTW)                                                     \
    const uint2* Bp = Bfrag + ((size_t)ntbase * KT_total + kt0) * 32 + lane;   \
    uint2 bcur[NTW], bnxt[NTW];                                                \
    _Pragma("unroll")                                                          \
    for (int q = 0; q < (NTW); q++) bcur[q] = Bp[(size_t)q * KT_total * 32];   \
    for (int kt = 0; kt < (KTS); kt++) {                                       \
        if (kt + 1 < (KTS)) {                                                  \
            _Pragma("unroll")                                                  \
            for (int q = 0; q < (NTW); q++)                                    \
                bnxt[q] = Bp[((size_t)q * KT_total + kt + 1) * 32];            \
        }                                                                      \
        uint4 A0 = *reinterpret_cast<const uint4*>(                            \
            &Af[(kt * 2 + 0) * 128 + lane * 4]);                               \
        uint4 A1 = *reinterpret_cast<const uint4*>(                            \
            &Af[(kt * 2 + 1) * 128 + lane * 4]);                               \
        _Pragma("unroll")                                                      \
        for (int q = 0; q < (NTW); q++) {                                      \
            mma16816(acc[q][0], A0, bcur[q]);                                  \
            mma16816(acc[q][1], A1, bcur[q]);                                  \
        }                                                                      \
        _Pragma("unroll")                                                      \
        for (int q = 0; q < (NTW); q++) bcur[q] = bnxt[q];                     \
    }

#define MMA_WRITE_PART(NTW, Co, N)                                             \
    {                                                                          \
        int gg_ = lane >> 2, tg_ = lane & 3;                                   \
        _Pragma("unroll")                                                      \
        for (int q = 0; q < (NTW); q++) {                                      \
            int ncol = (ntbase + q) * 8 + tg_ * 2;                             \
            _Pragma("unroll")                                                  \
            for (int mt = 0; mt < 2; mt++) {                                   \
                int row = mt * 16 + gg_;                                       \
                *reinterpret_cast<float2*>((Co) + (size_t)row * (N) + ncol) =  \
                    make_float2(acc[q][mt][0], acc[q][mt][1]);                 \
                *reinterpret_cast<float2*>((Co) + (size_t)(row + 8) * (N) + ncol) = \
                    make_float2(acc[q][mt][2], acc[q][mt][3]);                 \
            }                                                                  \
        }                                                                      \
    }

// =========================================================================
// Gates GEMM + fused LSTM cell. grid = (32 n-groups, S k-slices), 128 thr.
// B is gate-permuted so n-group p holds gates i,f,g,o of units [32p,32p+32).
// =========================================================================
__global__ void __launch_bounds__(128) k_gates_mma(
    const uint2* __restrict__ Bfrag, int KT_total,
    const float* __restrict__ srcA0, const float* __restrict__ srcA1, int bnd,
    int gather, const int* __restrict__ tokptr, int tokstride,
    const float* __restrict__ bias, int S, int t, int store_enc,
    int* __restrict__ cnt)
{
    __shared__ unsigned Af[16 * 256];
    __shared__ int toks[32];
    __shared__ int s_last;
    const int tid = threadIdx.x;
    const int lane = tid & 31, warp = tid >> 5;
    const int kt0 = blockIdx.y * 16;
    const int c0 = kt0 * 16;

    if (tid < 32) toks[tid] = gather ? tokptr[tid * tokstride] : 0;
    __syncthreads();
    MMA_STAGE_A(16)
    __syncthreads();

    const int ntbase = (blockIdx.x * 4 + warp) * 4;
    float acc[4][2][4];
#pragma unroll
    for (int q = 0; q < 4; q++)
#pragma unroll
        for (int mt = 0; mt < 2; mt++)
#pragma unroll
            for (int u = 0; u < 4; u++) acc[q][mt][u] = 0.f;
    MMA_MAIN(16, 4)

    float* Co = g_gp + (size_t)blockIdx.y * BB * G4;
    MMA_WRITE_PART(4, Co, G4)

    // ---- arrival: last k-slice block for this n-group runs the cell ----
    __threadfence();
    __syncthreads();
    if (tid == 0) s_last = atomicAdd(&cnt[t * 32 + blockIdx.x], 1);
    __syncthreads();
    if (s_last != S - 1) return;
    __threadfence();

    const int p = blockIdx.x;
    for (int it = tid; it < 1024; it += 128) {
        int row = it >> 5, u = it & 31;
        int d = (p << 5) + u;
        float ig = bias[d], fg = bias[d + DH], gg = bias[d + 2 * DH], og = bias[d + 3 * DH];
        int base = (p << 7) + u;
        for (int s = 0; s < S; s++) {
            const float* gp = g_gp + (size_t)s * BB * G4 + (size_t)row * G4 + base;
            ig += gp[0]; fg += gp[32]; gg += gp[64]; og += gp[96];
        }
        int hi_ = row * DH + d;
        float c = g_c[hi_];
        c = sigm(fg) * c + sigm(ig) * tanhf(gg);
        float h = sigm(og) * tanhf(c);
        g_c[hi_] = c;
        g_h[hi_] = h;
        if (store_enc) g_enc_outs[(size_t)t * BB * DH + hi_] = h;
    }
}

// =========================================================================
// comb GEMM + fused bias/ReLU. grid = (8, 8), 128 thr.
// =========================================================================
__global__ void __launch_bounds__(128) k_comb_mma(
    const uint2* __restrict__ Bfrag, int KT_total,
    const float* __restrict__ srcA0, const float* __restrict__ srcA1, int bnd,
    const int* __restrict__ tokptr,
    const float* __restrict__ bias, int t, int* __restrict__ cnt)
{
    __shared__ unsigned Af[16 * 256];
    __shared__ int toks[32];
    __shared__ int s_last;
    const int tid = threadIdx.x;
    const int lane = tid & 31, warp = tid >> 5;
    const int kt0 = blockIdx.y * 16;
    const int c0 = kt0 * 16;
    const int gather = 1;

    if (tid < 32) toks[tid] = tokptr[tid];
    __syncthreads();
    MMA_STAGE_A(16)
    __syncthreads();

    const int ntbase = (blockIdx.x * 4 + warp) * 4;
    float acc[4][2][4];
#pragma unroll
    for (int q = 0; q < 4; q++)
#pragma unroll
        for (int mt = 0; mt < 2; mt++)
#pragma unroll
            for (int u = 0; u < 4; u++) acc[q][mt][u] = 0.f;
    MMA_MAIN(16, 4)

    float* Co = g_cpp + (size_t)blockIdx.y * BB * DH;
    MMA_WRITE_PART(4, Co, DH)

    __threadfence();
    __syncthreads();
    if (tid == 0) s_last = atomicAdd(&cnt[t * 8 + blockIdx.x], 1);
    __syncthreads();
    if (s_last != 7) return;
    __threadfence();

    const int p = blockIdx.x;
    for (int it = tid; it < 4096; it += 128) {
        int row = it >> 7, jj = it & 127;
        int j = (p << 7) + jj;
        float s = bias[j];
#pragma unroll
        for (int u = 0; u < 8; u++)
            s += g_cpp[(size_t)u * BB * DH + (size_t)row * DH + j];
        g_inp[row * DH + j] = fmaxf(s, 0.f);
    }
}

// =========================================================================
// out projection, 2-way K-split, fused finalize (bias + store + partial lse/argmax)
// grid = (125, 2), 128 thr. Block covers 256 cols.
// =========================================================================
__global__ void __launch_bounds__(128) k_outproj_mma(
    const uint2* __restrict__ Bfrag,
    const float* __restrict__ out_b, float* __restrict__ out, int t,
    int* __restrict__ cnt)
{
    __shared__ unsigned Af[32 * 256];   // reused as float vals[32][256] later
    __shared__ int s_last;
    const int tid = threadIdx.x;
    const int lane = tid & 31, warp = tid >> 5;
    const int KT_total = 64;
    const int kt0 = blockIdx.y * 32;
    const int c0 = kt0 * 16;
    const int bnd = DH, gather = 0;
    const float* srcA0 = g_h;
    const float* srcA1 = g_h;
    const int* toks = nullptr; (void)toks;

    // stage A (no gather)
    for (int i = tid; i < 32 * 256; i += 128) {
        int r = i & 3, ln = (i >> 2) & 31, mt = (i >> 7) & 1, kt = i >> 8;
        int gg_ = ln >> 2, tg_ = ln & 3;
        int row = mt * 16 + gg_ + ((r & 1) << 3);
        int colG = c0 + kt * 16 + tg_ * 2 + ((r >> 1) << 3);
        float2 v = *reinterpret_cast<const float2*>(srcA0 + (size_t)row * DH + colG);
        Af[i] = packbf(v.x, v.y);
    }
    (void)srcA1; (void)bnd; (void)gather;
    __syncthreads();

    const int ntbase = (blockIdx.x * 4 + warp) * 8;
    float acc[8][2][4];
#pragma unroll
    for (int q = 0; q < 8; q++)
#pragma unroll
        for (int mt = 0; mt < 2; mt++)
#pragma unroll
            for (int u = 0; u < 4; u++) acc[q][mt][u] = 0.f;
    MMA_MAIN(32, 8)

    float* Co = g_lg + (size_t)blockIdx.y * BB * VV;
    MMA_WRITE_PART(8, Co, VV)

    __threadfence();
    __syncthreads();
    if (tid == 0) s_last = atomicAdd(&cnt[t * NPO + blockIdx.x], 1);
    __syncthreads();
    if (s_last != 1) return;
    __threadfence();

    // finalize: vals = my acc + other slice partial + bias; store; stage to smem
    const float* other = g_lg + (size_t)(1 - blockIdx.y) * BB * VV;
    float (*vals)[256] = reinterpret_cast<float (*)[256]>(Af);
    __syncthreads();   // everyone past mma; Af safe to reuse
    {
        int gg_ = lane >> 2, tg_ = lane & 3;
#pragma unroll
        for (int q = 0; q < 8; q++) {
            int ncol = (ntbase + q) * 8 + tg_ * 2;
            int lcol = ncol - blockIdx.x * 256;
#pragma unroll
            for (int mt = 0; mt < 2; mt++) {
#pragma unroll
                for (int half = 0; half < 2; half++) {
                    int row = mt * 16 + gg_ + half * 8;
#pragma unroll
                    for (int cc = 0; cc < 2; cc++) {
                        float v = acc[q][mt][half * 2 + cc]
                                + other[(size_t)row * VV + ncol + cc]
                                + out_b[ncol + cc];
                        out[((size_t)row * LL + t) * VV + ncol + cc] = v;
                        vals[row][lcol + cc] = v;
                    }
                }
            }
        }
    }
    __syncthreads();

    // per-row partial lse / argmax over this block's 256 cols
    for (int r8 = 0; r8 < 8; r8++) {
        int row = warp * 8 + r8;
        float s = 0.f, m = -1e30f;
        int mi = 0x7fffffff;
#pragma unroll
        for (int k = 0; k < 8; k++) {
            int c = lane + 32 * k;
            float v = vals[row][c];
            s += expf(v);
            if (v > m) { m = v; mi = blockIdx.x * 256 + c; }
        }
#pragma unroll
        for (int o = 16; o; o >>= 1) {
            s += __shfl_down_sync(0xffffffffu, s, o);
            float om = __shfl_down_sync(0xffffffffu, m, o);
            int   oi = __shfl_down_sync(0xffffffffu, mi, o);
            if (om > m || (om == m && oi < mi)) { m = om; mi = oi; }
        }
        if (lane == 0) {
            g_psum[row * NPO + blockIdx.x] = s;
            g_pmax[row * NPO + blockIdx.x] = m;
            g_pidx[row * NPO + blockIdx.x] = mi;
        }
    }
}

// =========================================================================
// Fused attention: gather e, scores (f32), softmax, context. 1 block / b.
// =========================================================================
__global__ void __launch_bounds__(256) k_attn(
    const float* __restrict__ dec_embed,
    const float* __restrict__ attn_w,
    const float* __restrict__ attn_b)
{
    __shared__ float cat_s[2 * DH];
    __shared__ float sp[4][LL];
    __shared__ float sc[LL], exs[LL], aw[LL];
    const int b = blockIdx.x, tid = threadIdx.x;
    const int tok = g_tok[b];

    for (int i = tid; i < DH; i += 256) {
        cat_s[i] = dec_embed[(size_t)tok * DH + i];
        cat_s[DH + i] = g_h[b * DH + i];
    }
    __syncthreads();
    {
        int l = tid & 63, kc = tid >> 6;
        float s = 0.f;
        const float* wp = attn_w + l;
        int k0 = kc * 512;
#pragma unroll 8
        for (int k = 0; k < 512; k++)
            s += cat_s[k0 + k] * wp[(size_t)(k0 + k) * LL];
        sp[kc][l] = s;
    }
    __syncthreads();
    if (tid < LL)
        sc[tid] = attn_b[tid] + sp[0][tid] + sp[1][tid] + sp[2][tid] + sp[3][tid];
    __syncthreads();
    if (tid < LL) {
        float m = -1e30f;
        for (int i = 0; i < LL; i++) m = fmaxf(m, sc[i]);
        exs[tid] = expf(sc[tid] - m);
    }
    __syncthreads();
    if (tid < LL) {
        float tot = 0.f;
        for (int i = 0; i < LL; i++) tot += exs[i];
        aw[tid] = exs[tid] / tot;
    }
    __syncthreads();
    for (int d = tid; d < DH; d += 256) {
        float s = 0.f;
        const float* ep = g_enc_outs + b * DH + d;
#pragma unroll 8
        for (int l = 0; l < LL; l++) s += aw[l] * ep[(size_t)l * BB * DH];
        g_ctx[b * DH + d] = s;
    }
}

// ---------------- reduce 125 partials -> lse + token ----------------
__global__ void k_reduce(int t) {
    __shared__ float ss[128], sm[128];
    __shared__ int   si[128];
    int b = blockIdx.x, tid = threadIdx.x;
    float s = 0.f, m = -1e30f;
    int mi = 0x7fffffff;
    for (int i = tid; i < NPO; i += 128) {
        s += g_psum[b * NPO + i];
        float om = g_pmax[b * NPO + i];
        int oi = g_pidx[b * NPO + i];
        if (om > m || (om == m && oi < mi)) { m = om; mi = oi; }
    }
    ss[tid] = s; sm[tid] = m; si[tid] = mi;
    __syncthreads();
    for (int o = 64; o; o >>= 1) {
        if (tid < o) {
            ss[tid] += ss[tid + o];
            if (sm[tid + o] > sm[tid] ||
                (sm[tid + o] == sm[tid] && si[tid + o] < si[tid])) {
                sm[tid] = sm[tid + o];
                si[tid] = si[tid + o];
            }
        }
        __syncthreads();
    }
    if (tid == 0) {
        g_lse[t * BB + b] = logf(ss[0]);
        g_tok[b] = si[0];
    }
}

// ---------------- final pass: out -= lse ----------------
__global__ void k_finalize(float* __restrict__ out) {
    long idx = (long)blockIdx.x * blockDim.x + threadIdx.x;
    if (idx < (long)BB * LL * VV) {
        long r = idx / VV;
        int t = (int)(r % LL);
        int b = (int)(r / LL);
        out[idx] -= g_lse[t * BB + b];
    }
}

// ---------------- host orchestration ----------------
extern "C" void kernel_launch(void* const* d_in, const int* in_sizes, int n_in,
                              void* d_out, int out_size) {
    const int*   x         = (const int*)  d_in[0];
    const float* enc_embed = (const float*)d_in[1];
    const float* enc_wx    = (const float*)d_in[2];
    const float* enc_wh    = (const float*)d_in[3];
    const float* enc_b     = (const float*)d_in[4];
    const float* dec_embed = (const float*)d_in[5];
    const float* attn_w    = (const float*)d_in[6];
    const float* attn_b    = (const float*)d_in[7];
    const float* comb_w    = (const float*)d_in[8];
    const float* comb_b    = (const float*)d_in[9];
    const float* dec_wx    = (const float*)d_in[10];
    const float* dec_wh    = (const float*)d_in[11];
    const float* dec_b     = (const float*)d_in[12];
    const float* out_w     = (const float*)d_in[13];
    const float* out_b     = (const float*)d_in[14];
    float* out = (float*)d_out;

    uint2 *pBout, *pBdec, *pBenc, *pBcomb;
    float *p_h, *p_inp, *p_ctx;
    int *p_tok, *p_ce, *p_cd, *p_cc, *p_co;
    cudaGetSymbolAddress((void**)&pBout, Bout);
    cudaGetSymbolAddress((void**)&pBdec, Bdec);
    cudaGetSymbolAddress((void**)&pBenc, Benc);
    cudaGetSymbolAddress((void**)&pBcomb, Bcomb);
    cudaGetSymbolAddress((void**)&p_h, g_h);
    cudaGetSymbolAddress((void**)&p_inp, g_inp);
    cudaGetSymbolAddress((void**)&p_ctx, g_ctx);
    cudaGetSymbolAddress((void**)&p_tok, g_tok);
    cudaGetSymbolAddress((void**)&p_ce, g_cnt_enc);
    cudaGetSymbolAddress((void**)&p_cd, g_cnt_dec);
    cudaGetSymbolAddress((void**)&p_cc, g_cnt_comb);
    cudaGetSymbolAddress((void**)&p_co, g_cnt_out);

    // ---------- weight prep ----------
    k_prepB<<<32768, 256>>>(out_w, out_w, 1024, VV, 64, 4000, 0, pBout);
    k_prepB<<<8192, 256>>>(dec_wx, dec_wh, 1024, G4, 128, 512, 1, pBdec);
    k_prepB<<<6144, 256>>>(enc_wx, enc_wh, 512, G4, 96, 512, 1, pBenc);
    k_prepB<<<2048, 256>>>(comb_w, comb_w, 2048, DH, 128, 128, 0, pBcomb);

    // ---------- encoder: 1 launch/step (gates mma + fused cell) ----------
    k_init<<<128, 256>>>(0);
    for (int t = 0; t < LL; t++) {
        k_gates_mma<<<dim3(32, 6), 128>>>(pBenc, 96, enc_embed, p_h, 512,
                                          1, x + t, LL, enc_b, 6, t, 1, p_ce);
    }

    // ---------- decoder: 5 launches/step ----------
    k_init<<<128, 256>>>(1);
    for (int t = 0; t < LL; t++) {
        k_attn<<<BB, 256>>>(dec_embed, attn_w, attn_b);
        k_comb_mma<<<dim3(8, 8), 128>>>(pBcomb, 128, dec_embed, p_ctx, 1024,
                                        p_tok, comb_b, t, p_cc);
        k_gates_mma<<<dim3(32, 8), 128>>>(pBdec, 128, p_inp, p_h, 1024,
                                          0, p_tok, 1, dec_b, 8, t, 0, p_cd);
        k_outproj_mma<<<dim3(NPO, 2), 128>>>(pBout, out_b, out, t, p_co);
        k_reduce<<<BB, 128>>>(t);
    }

    long total = (long)BB * LL * VV;
    k_finalize<<<(int)((total + 255) / 256), 256>>>(out);
}

// round 6
// speedup vs baseline: 11.7526x; 1.1756x over previous
#include <cuda_runtime.h>
#include <cuda_bf16.h>
#include <math.h>

#define BB 32
#define EMB 512
#define DH 1024
#define LL 64
#define VV 32000
#define G4 4096
#define NPO 125          // outproj blocks (256 cols each)

// ---------------- bf16 fragment weights ----------------
__device__ uint2 Bout[(size_t)4000 * 64 * 32];
__device__ uint2 Bdec[(size_t)512 * 128 * 32];   // gate-permuted cols
__device__ uint2 Benc[(size_t)512 * 96 * 32];    // gate-permuted cols
__device__ uint2 Bcomb[(size_t)128 * 128 * 32];
__device__ float g_attnT[LL * 2 * DH];           // attn_w transposed [l][k]

// ---------------- state / partials ----------------
__device__ float g_h[BB * DH];
__device__ float g_c[BB * DH];
__device__ float g_inp[BB * DH];
__device__ float g_ctx[BB * DH];
__device__ float g_eo2[BB * LL * DH];        // enc outs [b][l][d]
__device__ float g_gp[8 * BB * G4];
__device__ float g_cpp[8 * BB * DH];
__device__ float g_psum[BB * NPO];
__device__ float g_pmax[BB * NPO];
__device__ int   g_pidx[BB * NPO];
__device__ int   g_tok[BB];
__device__ float g_lse[LL * BB];
__device__ int g_cnt_enc[LL * 16];
__device__ int g_cnt_dec[LL * 16];
__device__ int g_cnt_comb[LL * 4];

// ---------------- helpers ----------------
__device__ __forceinline__ unsigned packbf(float x, float y) {
    unsigned lo = __bfloat16_as_ushort(__float2bfloat16_rn(x));
    unsigned hi = __bfloat16_as_ushort(__float2bfloat16_rn(y));
    return lo | (hi << 16);
}
__device__ __forceinline__ void mma16816(float* c, uint4 a, uint2 b) {
    asm volatile(
        "mma.sync.aligned.m16n8k16.row.col.f32.bf16.bf16.f32 "
        "{%0,%1,%2,%3}, {%4,%5,%6,%7}, {%8,%9}, {%0,%1,%2,%3};"
        : "+f"(c[0]), "+f"(c[1]), "+f"(c[2]), "+f"(c[3])
        : "r"(a.x), "r"(a.y), "r"(a.z), "r"(a.w), "r"(b.x), "r"(b.y));
}
__device__ __forceinline__ float sigm(float x) { return 1.f / (1.f + expf(-x)); }

// ---------------- init ----------------
__global__ void k_init(int phase) {
    int i = blockIdx.x * blockDim.x + threadIdx.x;
    if (i < BB * DH) { g_h[i] = 0.f; g_c[i] = 0.f; }
    if (phase == 0) {
        if (i < LL * 16) { g_cnt_enc[i] = 0; g_cnt_dec[i] = 0; }
        if (i < LL * 4)  g_cnt_comb[i] = 0;
    } else {
        if (i < BB) g_tok[i] = 127;
    }
}

// ---------------- weight prep ----------------
__global__ void k_prepB(const float* __restrict__ W0, const float* __restrict__ W1,
                        int kbnd, int N, int KTOT, int NT, int perm,
                        uint2* __restrict__ dst) {
    size_t idx = (size_t)blockIdx.x * blockDim.x + threadIdx.x;
    size_t total = (size_t)NT * KTOT * 32;
    if (idx >= total) return;
    int lane = (int)(idx & 31);
    int kt = (int)((idx >> 5) % KTOT);
    int nt = (int)(idx / ((size_t)KTOT * 32));
    int g = lane >> 2, tg = lane & 3;
    int n = nt * 8 + g;
    if (perm) {
        int p = n >> 7, r = n & 127, gate = r >> 5, u = r & 31;
        n = gate * DH + (p << 5) + u;
    }
    int kb = kt * 16 + tg * 2;
    float w[4];
#pragma unroll
    for (int u = 0; u < 4; u++) {
        int k = kb + ((u >> 1) << 3) + (u & 1);
        w[u] = (k < kbnd) ? W0[(size_t)k * N + n] : W1[(size_t)(k - kbnd) * N + n];
    }
    dst[idx] = make_uint2(packbf(w[0], w[1]), packbf(w[2], w[3]));
}

__global__ void k_prepAttnT(const float* __restrict__ attn_w) {
    int idx = blockIdx.x * blockDim.x + threadIdx.x;
    if (idx < LL * 2 * DH) {
        int l = idx >> 11, k = idx & 2047;
        g_attnT[idx] = attn_w[(size_t)k * LL + l];
    }
}

// ---------------- shared mma macro pieces (256-thread blocks, 8 warps) ----------------
#define MMA_STAGE_A(KTS, NTHR)                                                 \
    for (int i = tid; i < (KTS) * 256; i += (NTHR)) {                          \
        int r = i & 3, ln = (i >> 2) & 31, mt = (i >> 7) & 1, kt = i >> 8;     \
        int gg_ = ln >> 2, tg_ = ln & 3;                                       \
        int row = mt * 16 + gg_ + ((r & 1) << 3);                              \
        int colG = c0 + kt * 16 + tg_ * 2 + ((r >> 1) << 3);                   \
        float2 v;                                                              \
        if (colG < bnd) {                                                      \
            const float* base = gather                                         \
                ? srcA0 + (size_t)toks[row] * bnd + colG                       \
                : srcA0 + (size_t)row * bnd + colG;                            \
            v = *reinterpret_cast<const float2*>(base);                        \
        } else {                                                               \
            v = *reinterpret_cast<const float2*>(                              \
                srcA1 + (size_t)row * DH + (colG - bnd));                      \
        }                                                                      \
        Af[i] = packbf(v.x, v.y);                                              \
    }

#define MMA_MAIN(KTS, NTW)                                                     \
    {                                                                          \
        const uint2* Bp = Bfrag + ((size_t)ntbase * KT_total + kt0) * 32 + lane;\
        uint2 bcur[NTW], bnxt[NTW];                                            \
        _Pragma("unroll")                                                      \
        for (int q = 0; q < (NTW); q++) bcur[q] = Bp[(size_t)q * KT_total * 32];\
        for (int kt = 0; kt < (KTS); kt++) {                                   \
            if (kt + 1 < (KTS)) {                                              \
                _Pragma("unroll")                                              \
                for (int q = 0; q < (NTW); q++)                                \
                    bnxt[q] = Bp[((size_t)q * KT_total + kt + 1) * 32];        \
            }                                                                  \
            uint4 A0 = *reinterpret_cast<const uint4*>(                        \
                &Af[(kt * 2 + 0) * 128 + lane * 4]);                           \
            uint4 A1 = *reinterpret_cast<const uint4*>(                        \
                &Af[(kt * 2 + 1) * 128 + lane * 4]);                           \
            _Pragma("unroll")                                                  \
            for (int q = 0; q < (NTW); q++) {                                  \
                mma16816(acc[q][0], A0, bcur[q]);                              \
                mma16816(acc[q][1], A1, bcur[q]);                              \
            }                                                                  \
            _Pragma("unroll")                                                  \
            for (int q = 0; q < (NTW); q++) bcur[q] = bnxt[q];                 \
        }                                                                      \
    }

#define MMA_WRITE_PART(NTW, Co, N)                                             \
    {                                                                          \
        int gg_ = lane >> 2, tg_ = lane & 3;                                   \
        _Pragma("unroll")                                                      \
        for (int q = 0; q < (NTW); q++) {                                      \
            int ncol = (ntbase + q) * 8 + tg_ * 2;                             \
            _Pragma("unroll")                                                  \
            for (int mt = 0; mt < 2; mt++) {                                   \
                int row = mt * 16 + gg_;                                       \
                *reinterpret_cast<float2*>((Co) + (size_t)row * (N) + ncol) =  \
                    make_float2(acc[q][mt][0], acc[q][mt][1]);                 \
                *reinterpret_cast<float2*>((Co) + (size_t)(row + 8) * (N) + ncol) = \
                    make_float2(acc[q][mt][2], acc[q][mt][3]);                 \
            }                                                                  \
        }                                                                      \
    }

// =========================================================================
// Gates GEMM + fused LSTM cell. grid = (16, S), 256 thr (8 warps).
// Block covers 256 permuted cols = 2 n-groups (64 hidden units).
// =========================================================================
__global__ void __launch_bounds__(256) k_gates_mma(
    const uint2* __restrict__ Bfrag, int KT_total,
    const float* __restrict__ srcA0, const float* __restrict__ srcA1, int bnd,
    int gather, const int* __restrict__ tokptr, int tokstride,
    const float* __restrict__ bias, int S, int t, int store_enc,
    int* __restrict__ cnt)
{
    __shared__ unsigned Af[16 * 256];
    __shared__ int toks[32];
    __shared__ int s_last;
    const int tid = threadIdx.x;
    const int lane = tid & 31, warp = tid >> 5;
    const int kt0 = blockIdx.y * 16;
    const int c0 = kt0 * 16;

    if (tid < 32) toks[tid] = gather ? tokptr[tid * tokstride] : 0;
    __syncthreads();
    MMA_STAGE_A(16, 256)
    __syncthreads();

    const int ntbase = blockIdx.x * 32 + warp * 4;
    float acc[4][2][4];
#pragma unroll
    for (int q = 0; q < 4; q++)
#pragma unroll
        for (int mt = 0; mt < 2; mt++)
#pragma unroll
            for (int u = 0; u < 4; u++) acc[q][mt][u] = 0.f;
    MMA_MAIN(16, 4)

    float* Co = g_gp + (size_t)blockIdx.y * BB * G4;
    MMA_WRITE_PART(4, Co, G4)

    __threadfence();
    __syncthreads();
    if (tid == 0) s_last = atomicAdd(&cnt[t * 16 + blockIdx.x], 1);
    __syncthreads();
    if (s_last != S - 1) return;
    __threadfence();

    const int bx = blockIdx.x;
    for (int it = tid; it < 2048; it += 256) {
        int row = it >> 6, uu = it & 63;
        int P = 2 * bx + (uu >> 5), u = uu & 31;
        int base = (P << 7) + u;
        int d = (P << 5) + u;
        float ig = bias[d], fg = bias[d + DH], gg = bias[d + 2 * DH], og = bias[d + 3 * DH];
        for (int s = 0; s < S; s++) {
            const float* gp = g_gp + (size_t)s * BB * G4 + (size_t)row * G4 + base;
            ig += gp[0]; fg += gp[32]; gg += gp[64]; og += gp[96];
        }
        int hi_ = row * DH + d;
        float c = g_c[hi_];
        c = sigm(fg) * c + sigm(ig) * tanhf(gg);
        float h = sigm(og) * tanhf(c);
        g_c[hi_] = c;
        g_h[hi_] = h;
        if (store_enc) g_eo2[((size_t)row * LL + t) * DH + d] = h;
    }
}

// =========================================================================
// comb GEMM + fused bias/ReLU. grid = (4, 8), 256 thr.
// =========================================================================
__global__ void __launch_bounds__(256) k_comb_mma(
    const uint2* __restrict__ Bfrag, int KT_total,
    const float* __restrict__ srcA0, const float* __restrict__ srcA1, int bnd,
    const int* __restrict__ tokptr,
    const float* __restrict__ bias, int t, int* __restrict__ cnt)
{
    __shared__ unsigned Af[16 * 256];
    __shared__ int toks[32];
    __shared__ int s_last;
    const int tid = threadIdx.x;
    const int lane = tid & 31, warp = tid >> 5;
    const int kt0 = blockIdx.y * 16;
    const int c0 = kt0 * 16;
    const int gather = 1;

    if (tid < 32) toks[tid] = tokptr[tid];
    __syncthreads();
    MMA_STAGE_A(16, 256)
    __syncthreads();

    const int ntbase = blockIdx.x * 32 + warp * 4;
    float acc[4][2][4];
#pragma unroll
    for (int q = 0; q < 4; q++)
#pragma unroll
        for (int mt = 0; mt < 2; mt++)
#pragma unroll
            for (int u = 0; u < 4; u++) acc[q][mt][u] = 0.f;
    MMA_MAIN(16, 4)

    float* Co = g_cpp + (size_t)blockIdx.y * BB * DH;
    MMA_WRITE_PART(4, Co, DH)

    __threadfence();
    __syncthreads();
    if (tid == 0) s_last = atomicAdd(&cnt[t * 4 + blockIdx.x], 1);
    __syncthreads();
    if (s_last != 7) return;
    __threadfence();

    for (int it = tid; it < 8192; it += 256) {
        int row = it >> 8, jj = it & 255;
        int j = blockIdx.x * 256 + jj;
        float s = bias[j];
#pragma unroll
        for (int u = 0; u < 8; u++)
            s += g_cpp[(size_t)u * BB * DH + (size_t)row * DH + j];
        g_inp[row * DH + j] = fmaxf(s, 0.f);
    }
}

// =========================================================================
// out projection: single kernel, full K (two A-chunks), fused finalize.
// grid = 125, 256 thr; block covers 256 cols.
// =========================================================================
__global__ void __launch_bounds__(256) k_outproj_mma(
    const uint2* __restrict__ Bfrag,
    const float* __restrict__ out_b, float* __restrict__ out, int t)
{
    __shared__ unsigned Af[32 * 256];   // 32 KB; reused as vals[32][256]
    const int tid = threadIdx.x;
    const int lane = tid & 31, warp = tid >> 5;
    const int KT_total = 64;
    const int ntbase = blockIdx.x * 32 + warp * 4;

    float acc[4][2][4];
#pragma unroll
    for (int q = 0; q < 4; q++)
#pragma unroll
        for (int mt = 0; mt < 2; mt++)
#pragma unroll
            for (int u = 0; u < 4; u++) acc[q][mt][u] = 0.f;

#pragma unroll 1
    for (int chunk = 0; chunk < 2; chunk++) {
        const int c0 = chunk * 512;
        __syncthreads();
        for (int i = tid; i < 32 * 256; i += 256) {
            int r = i & 3, ln = (i >> 2) & 31, mt = (i >> 7) & 1, kt = i >> 8;
            int gg_ = ln >> 2, tg_ = ln & 3;
            int row = mt * 16 + gg_ + ((r & 1) << 3);
            int colG = c0 + kt * 16 + tg_ * 2 + ((r >> 1) << 3);
            float2 v = *reinterpret_cast<const float2*>(g_h + (size_t)row * DH + colG);
            Af[i] = packbf(v.x, v.y);
        }
        __syncthreads();
        const int kt0 = chunk * 32;
        MMA_MAIN(32, 4)
    }

    __syncthreads();
    float (*vals)[256] = reinterpret_cast<float (*)[256]>(Af);
    {
        int gg_ = lane >> 2, tg_ = lane & 3;
#pragma unroll
        for (int q = 0; q < 4; q++) {
            int ncol = (ntbase + q) * 8 + tg_ * 2;
            int lcol = (warp * 4 + q) * 8 + tg_ * 2;
#pragma unroll
            for (int mt = 0; mt < 2; mt++) {
#pragma unroll
                for (int half = 0; half < 2; half++) {
                    int row = mt * 16 + gg_ + half * 8;
#pragma unroll
                    for (int cc = 0; cc < 2; cc++) {
                        float v = acc[q][mt][half * 2 + cc] + out_b[ncol + cc];
                        out[((size_t)row * LL + t) * VV + ncol + cc] = v;
                        vals[row][lcol + cc] = v;
                    }
                }
            }
        }
    }
    __syncthreads();

    // 8 warps × 4 rows: partial lse/argmax over this block's 256 cols
#pragma unroll
    for (int r4 = 0; r4 < 4; r4++) {
        int row = warp * 4 + r4;
        float s = 0.f, m = -1e30f;
        int mi = 0x7fffffff;
#pragma unroll
        for (int k = 0; k < 8; k++) {
            int c = lane + 32 * k;
            float v = vals[row][c];
            s += expf(v);
            if (v > m) { m = v; mi = blockIdx.x * 256 + c; }
        }
#pragma unroll
        for (int o = 16; o; o >>= 1) {
            s += __shfl_down_sync(0xffffffffu, s, o);
            float om = __shfl_down_sync(0xffffffffu, m, o);
            int   oi = __shfl_down_sync(0xffffffffu, mi, o);
            if (om > m || (om == m && oi < mi)) { m = om; mi = oi; }
        }
        if (lane == 0) {
            g_psum[row * NPO + blockIdx.x] = s;
            g_pmax[row * NPO + blockIdx.x] = m;
            g_pidx[row * NPO + blockIdx.x] = mi;
        }
    }
}

// =========================================================================
// Fused attention: gather e, scores (float4 over attn_wT), softmax, ctx.
// =========================================================================
__global__ void __launch_bounds__(256) k_attn(
    const float* __restrict__ dec_embed,
    const float* __restrict__ attn_b)
{
    __shared__ float cat_s[2 * DH];
    __shared__ float sp[4][LL];
    __shared__ float sc[LL], exs[LL], aw[LL];
    const int b = blockIdx.x, tid = threadIdx.x;
    const int tok = g_tok[b];

    for (int i = tid; i < DH; i += 256) {
        cat_s[i] = dec_embed[(size_t)tok * DH + i];
        cat_s[DH + i] = g_h[b * DH + i];
    }
    __syncthreads();
    {
        int l = tid & 63, kc = tid >> 6;
        int k0 = kc * 512;
        const float4* wp = reinterpret_cast<const float4*>(g_attnT + (size_t)l * 2048 + k0);
        const float4* cp = reinterpret_cast<const float4*>(cat_s + k0);
        float s = 0.f;
#pragma unroll 8
        for (int j = 0; j < 128; j++) {
            float4 w = wp[j];
            float4 c = cp[j];
            s += w.x * c.x + w.y * c.y + w.z * c.z + w.w * c.w;
        }
        sp[kc][l] = s;
    }
    __syncthreads();
    if (tid < LL)
        sc[tid] = attn_b[tid] + sp[0][tid] + sp[1][tid] + sp[2][tid] + sp[3][tid];
    __syncthreads();
    if (tid < LL) {
        float m = -1e30f;
        for (int i = 0; i < LL; i++) m = fmaxf(m, sc[i]);
        exs[tid] = expf(sc[tid] - m);
    }
    __syncthreads();
    if (tid < LL) {
        float tot = 0.f;
        for (int i = 0; i < LL; i++) tot += exs[i];
        aw[tid] = exs[tid] / tot;
    }
    __syncthreads();
    {
        int d0 = tid * 4;
        float4 a4 = make_float4(0.f, 0.f, 0.f, 0.f);
        const float4* ep = reinterpret_cast<const float4*>(g_eo2 + (size_t)b * LL * DH + d0);
#pragma unroll 8
        for (int l = 0; l < LL; l++) {
            float w = aw[l];
            float4 e = ep[(size_t)l * (DH / 4)];
            a4.x += w * e.x; a4.y += w * e.y; a4.z += w * e.z; a4.w += w * e.w;
        }
        *reinterpret_cast<float4*>(g_ctx + b * DH + d0) = a4;
    }
}

// ---------------- reduce 125 partials -> lse + token ----------------
__global__ void k_reduce(int t) {
    __shared__ float ss[128], sm[128];
    __shared__ int   si[128];
    int b = blockIdx.x, tid = threadIdx.x;
    float s = 0.f, m = -1e30f;
    int mi = 0x7fffffff;
    for (int i = tid; i < NPO; i += 128) {
        s += g_psum[b * NPO + i];
        float om = g_pmax[b * NPO + i];
        int oi = g_pidx[b * NPO + i];
        if (om > m || (om == m && oi < mi)) { m = om; mi = oi; }
    }
    ss[tid] = s; sm[tid] = m; si[tid] = mi;
    __syncthreads();
    for (int o = 64; o; o >>= 1) {
        if (tid < o) {
            ss[tid] += ss[tid + o];
            if (sm[tid + o] > sm[tid] ||
                (sm[tid + o] == sm[tid] && si[tid + o] < si[tid])) {
                sm[tid] = sm[tid + o];
                si[tid] = si[tid + o];
            }
        }
        __syncthreads();
    }
    if (tid == 0) {
        g_lse[t * BB + b] = logf(ss[0]);
        g_tok[b] = si[0];
    }
}

// ---------------- final pass: out -= lse ----------------
__global__ void k_finalize(float* __restrict__ out) {
    long idx = (long)blockIdx.x * blockDim.x + threadIdx.x;
    if (idx < (long)BB * LL * VV) {
        long r = idx / VV;
        int t = (int)(r % LL);
        int b = (int)(r / LL);
        out[idx] -= g_lse[t * BB + b];
    }
}

// ---------------- host orchestration ----------------
extern "C" void kernel_launch(void* const* d_in, const int* in_sizes, int n_in,
                              void* d_out, int out_size) {
    const int*   x         = (const int*)  d_in[0];
    const float* enc_embed = (const float*)d_in[1];
    const float* enc_wx    = (const float*)d_in[2];
    const float* enc_wh    = (const float*)d_in[3];
    const float* enc_b     = (const float*)d_in[4];
    const float* dec_embed = (const float*)d_in[5];
    const float* attn_w    = (const float*)d_in[6];
    const float* attn_b    = (const float*)d_in[7];
    const float* comb_w    = (const float*)d_in[8];
    const float* comb_b    = (const float*)d_in[9];
    const float* dec_wx    = (const float*)d_in[10];
    const float* dec_wh    = (const float*)d_in[11];
    const float* dec_b     = (const float*)d_in[12];
    const float* out_w     = (const float*)d_in[13];
    const float* out_b     = (const float*)d_in[14];
    float* out = (float*)d_out;

    uint2 *pBout, *pBdec, *pBenc, *pBcomb;
    float *p_h, *p_inp, *p_ctx;
    int *p_tok, *p_ce, *p_cd, *p_cc;
    cudaGetSymbolAddress((void**)&pBout, Bout);
    cudaGetSymbolAddress((void**)&pBdec, Bdec);
    cudaGetSymbolAddress((void**)&pBenc, Benc);
    cudaGetSymbolAddress((void**)&pBcomb, Bcomb);
    cudaGetSymbolAddress((void**)&p_h, g_h);
    cudaGetSymbolAddress((void**)&p_inp, g_inp);
    cudaGetSymbolAddress((void**)&p_ctx, g_ctx);
    cudaGetSymbolAddress((void**)&p_tok, g_tok);
    cudaGetSymbolAddress((void**)&p_ce, g_cnt_enc);
    cudaGetSymbolAddress((void**)&p_cd, g_cnt_dec);
    cudaGetSymbolAddress((void**)&p_cc, g_cnt_comb);

    // launches 1..3: init + encoder-needed preps, so that launches 4.. are the
    // hot k_gates_mma class (ncu -s 5 alignment robust to 0-3 harness launches)
    k_init<<<128, 256>>>(0);
    k_prepB<<<6144, 256>>>(enc_wx, enc_wh, 512, G4, 96, 512, 1, pBenc);
    k_prepB<<<2048, 256>>>(comb_w, comb_w, 2048, DH, 128, 128, 0, pBcomb);

    // ---------- encoder ----------
    for (int t = 0; t < LL; t++) {
        k_gates_mma<<<dim3(16, 6), 256>>>(pBenc, 96, enc_embed, p_h, 512,
                                          1, x + t, LL, enc_b, 6, t, 1, p_ce);
    }

    // remaining preps (needed by decoder only)
    k_prepB<<<32768, 256>>>(out_w, out_w, 1024, VV, 64, 4000, 0, pBout);
    k_prepB<<<8192, 256>>>(dec_wx, dec_wh, 1024, G4, 128, 512, 1, pBdec);
    k_prepAttnT<<<512, 256>>>(attn_w);

    // ---------- decoder ----------
    k_init<<<128, 256>>>(1);
    for (int t = 0; t < LL; t++) {
        k_attn<<<BB, 256>>>(dec_embed, attn_b);
        k_comb_mma<<<dim3(4, 8), 256>>>(pBcomb, 128, dec_embed, p_ctx, 1024,
                                        p_tok, comb_b, t, p_cc);
        k_gates_mma<<<dim3(16, 8), 256>>>(pBdec, 128, p_inp, p_h, 1024,
                                          0, p_tok, 1, dec_b, 8, t, 0, p_cd);
        k_outproj_mma<<<NPO, 256>>>(pBout, out_b, out, t);
        k_reduce<<<BB, 128>>>(t);
    }

    long total = (long)BB * LL * VV;
    k_finalize<<<(int)((total + 255) / 256), 256>>>(out);
}

// round 8
// speedup vs baseline: 13.4959x; 1.1483x over previous
#include <cuda_runtime.h>
#include <cuda_bf16.h>
#include <math.h>

#define BB 32
#define EMB 512
#define DH 1024
#define LL 64
#define VV 32000
#define G4 4096
#define NPO 125          // outproj n-blocks (256 cols each)

// ---------------- bf16 uint4 fragment weights: [nt][ktp][lane], 2 kt per uint4 ----------------
__device__ uint4 Bout4[(size_t)4000 * 32 * 32];
__device__ uint4 Bdec4[(size_t)512 * 64 * 32];   // gate-permuted cols
__device__ uint4 Benc4[(size_t)512 * 48 * 32];   // gate-permuted cols
__device__ uint4 Bcomb4[(size_t)128 * 64 * 32];
__device__ float g_attnT[LL * 2 * DH];

// ---------------- state / partials ----------------
__device__ float g_h[BB * DH];
__device__ float g_c[BB * DH];
__device__ float g_inp[BB * DH];
__device__ float g_ctx[BB * DH];
__device__ float g_eo2[BB * LL * DH];
__device__ float g_gp[16 * BB * G4];
__device__ float g_cpp[16 * BB * DH];
__device__ float g_lg[2 * BB * VV];
__device__ float g_psum[BB * NPO];
__device__ float g_pmax[BB * NPO];
__device__ int   g_pidx[BB * NPO];
__device__ int   g_tok[BB];
__device__ float g_lse[LL * BB];
__device__ int g_cnt_enc[LL * 16];
__device__ int g_cnt_dec[LL * 16];
__device__ int g_cnt_comb[LL * 4];
__device__ int g_cnt_out[LL * NPO];

// ---------------- helpers ----------------
__device__ __forceinline__ unsigned packbf(float x, float y) {
    unsigned lo = __bfloat16_as_ushort(__float2bfloat16_rn(x));
    unsigned hi = __bfloat16_as_ushort(__float2bfloat16_rn(y));
    return lo | (hi << 16);
}
__device__ __forceinline__ void mma16816(float* c, uint4 a, uint2 b) {
    asm volatile(
        "mma.sync.aligned.m16n8k16.row.col.f32.bf16.bf16.f32 "
        "{%0,%1,%2,%3}, {%4,%5,%6,%7}, {%8,%9}, {%0,%1,%2,%3};"
        : "+f"(c[0]), "+f"(c[1]), "+f"(c[2]), "+f"(c[3])
        : "r"(a.x), "r"(a.y), "r"(a.z), "r"(a.w), "r"(b.x), "r"(b.y));
}
__device__ __forceinline__ float sigm(float x) { return 1.f / (1.f + expf(-x)); }
__device__ __forceinline__ unsigned sptr(const void* p) {
    return (unsigned)__cvta_generic_to_shared(p);
}
__device__ __forceinline__ void cpa16(unsigned s, const void* g) {
    asm volatile("cp.async.cg.shared.global [%0], [%1], 16;" :: "r"(s), "l"(g));
}
#define CP_COMMIT() asm volatile("cp.async.commit_group;")
#define CP_WAIT0()  asm volatile("cp.async.wait_group 0;")
#define CP_WAIT1()  asm volatile("cp.async.wait_group 1;")

// ---------------- init ----------------
__global__ void k_init(int phase) {
    int i = blockIdx.x * blockDim.x + threadIdx.x;
    if (i < BB * DH) { g_h[i] = 0.f; g_c[i] = 0.f; }
    if (phase == 0) {
        if (i < LL * 16) { g_cnt_enc[i] = 0; g_cnt_dec[i] = 0; }
        if (i < LL * 4)  g_cnt_comb[i] = 0;
        if (i < LL * NPO) g_cnt_out[i] = 0;
    } else {
        if (i < BB) g_tok[i] = 127;
    }
}

// ---------------- B prep: W[k][n] f32 -> [nt][ktp][lane] uint4 (2 kt) ----------------
__global__ void k_prepB4(const float* __restrict__ W0, const float* __restrict__ W1,
                         int kbnd, int N, int KTPT, int NT, int perm,
                         uint4* __restrict__ dst) {
    size_t idx = (size_t)blockIdx.x * blockDim.x + threadIdx.x;
    size_t total = (size_t)NT * KTPT * 32;
    if (idx >= total) return;
    int lane = (int)(idx & 31);
    int ktp = (int)((idx >> 5) % KTPT);
    int nt = (int)(idx / ((size_t)KTPT * 32));
    int g = lane >> 2, tg = lane & 3;
    int n = nt * 8 + g;
    if (perm) {
        int p = n >> 7, r = n & 127, gate = r >> 5, u = r & 31;
        n = gate * DH + (p << 5) + u;
    }
    unsigned rr[4];
#pragma unroll
    for (int h = 0; h < 2; h++) {
        int kt = 2 * ktp + h;
        int kb = kt * 16 + tg * 2;
        float w[4];
#pragma unroll
        for (int u = 0; u < 4; u++) {
            int k = kb + ((u >> 1) << 3) + (u & 1);
            w[u] = (k < kbnd) ? W0[(size_t)k * N + n] : W1[(size_t)(k - kbnd) * N + n];
        }
        rr[2 * h] = packbf(w[0], w[1]);
        rr[2 * h + 1] = packbf(w[2], w[3]);
    }
    dst[idx] = make_uint4(rr[0], rr[1], rr[2], rr[3]);
}

__global__ void k_prepAttnT(const float* __restrict__ attn_w) {
    int idx = blockIdx.x * blockDim.x + threadIdx.x;
    if (idx < LL * 2 * DH) {
        int l = idx >> 11, k = idx & 2047;
        g_attnT[idx] = attn_w[(size_t)k * LL + l];
    }
}

// ---------------- A staging macro (per-lane fragment layout, bf16 pairs) ----------------
#define MMA_STAGE_A(KTS, NTHR)                                                 \
    for (int i = tid; i < (KTS) * 256; i += (NTHR)) {                          \
        int r = i & 3, ln = (i >> 2) & 31, mt = (i >> 7) & 1, kt = i >> 8;     \
        int gg_ = ln >> 2, tg_ = ln & 3;                                       \
        int row = mt * 16 + gg_ + ((r & 1) << 3);                              \
        int colG = c0 + kt * 16 + tg_ * 2 + ((r >> 1) << 3);                   \
        float2 v;                                                              \
        if (colG < bnd) {                                                      \
            const float* base = gather                                         \
                ? srcA0 + (size_t)toks[row] * bnd + colG                       \
                : srcA0 + (size_t)row * bnd + colG;                            \
            v = *reinterpret_cast<const float2*>(base);                        \
        } else {                                                               \
            v = *reinterpret_cast<const float2*>(                              \
                srcA1 + (size_t)row * DH + (colG - bnd));                      \
        }                                                                      \
        Af[i] = packbf(v.x, v.y);                                              \
    }

#define MMA_WRITE_PART(NTW, Co, N)                                             \
    {                                                                          \
        int gg_ = lane >> 2, tg_ = lane & 3;                                   \
        _Pragma("unroll")                                                      \
        for (int q = 0; q < (NTW); q++) {                                      \
            int ncol = (ntbase + q) * 8 + tg_ * 2;                             \
            _Pragma("unroll")                                                  \
            for (int mt = 0; mt < 2; mt++) {                                   \
                int row = mt * 16 + gg_;                                       \
                *reinterpret_cast<float2*>((Co) + (size_t)row * (N) + ncol) =  \
                    make_float2(acc[q][mt][0], acc[q][mt][1]);                 \
                *reinterpret_cast<float2*>((Co) + (size_t)(row + 8) * (N) + ncol) = \
                    make_float2(acc[q][mt][2], acc[q][mt][3]);                 \
            }                                                                  \
        }                                                                      \
    }

// consume one ktp (2 kt) from smem B for 4 n-tiles
#define MMA_CONSUME_KTP(ktpA, bidx)                                            \
    {                                                                          \
        uint4 A0 = *reinterpret_cast<const uint4*>(&Af[((ktpA) * 4 + 0) * 128 + lane * 4]); \
        uint4 A1 = *reinterpret_cast<const uint4*>(&Af[((ktpA) * 4 + 1) * 128 + lane * 4]); \
        uint4 A2 = *reinterpret_cast<const uint4*>(&Af[((ktpA) * 4 + 2) * 128 + lane * 4]); \
        uint4 A3 = *reinterpret_cast<const uint4*>(&Af[((ktpA) * 4 + 3) * 128 + lane * 4]); \
        _Pragma("unroll")                                                      \
        for (int q = 0; q < 4; q++) {                                          \
            uint4 b = Bs4[(bidx) + q * BSTRIDE + lane];                        \
            mma16816(acc[q][0], A0, make_uint2(b.x, b.y));                     \
            mma16816(acc[q][1], A1, make_uint2(b.x, b.y));                     \
            mma16816(acc[q][0], A2, make_uint2(b.z, b.w));                     \
            mma16816(acc[q][1], A3, make_uint2(b.z, b.w));                     \
        }                                                                      \
    }

// =========================================================================
// Gates GEMM + fused LSTM cell. grid = (16, S), 256 thr.
// Slice = 8 kt = 4 ktp (128 K). B staged fully in smem via cp.async (64KB).
// =========================================================================
__global__ void __launch_bounds__(256) k_gates_mma(
    const uint4* __restrict__ Bfrag4, int KTP_total,
    const float* __restrict__ srcA0, const float* __restrict__ srcA1, int bnd,
    int gather, const int* __restrict__ tokptr, int tokstride,
    const float* __restrict__ bias, int S, int t, int store_enc,
    int* __restrict__ cnt)
{
    extern __shared__ __align__(16) char dsm[];
    uint4* Bs4 = reinterpret_cast<uint4*>(dsm);              // 4096 uint4 = 64KB
    unsigned* Af = reinterpret_cast<unsigned*>(dsm + 65536); // 8KB
    __shared__ int toks[32];
    __shared__ int s_last;
    const int tid = threadIdx.x, lane = tid & 31, warp = tid >> 5;
    const int ktp0 = blockIdx.y * 4;
    const int c0 = ktp0 * 32;
    const int ntb = blockIdx.x * 32;

    // stage B (whole slice) via cp.async
    {
        unsigned sb = sptr(Bs4);
        const uint4* bbase = Bfrag4 + (size_t)ktp0 * 32;
        for (int i = tid; i < 4096; i += 256) {
            int nt_l = i >> 7, rem = i & 127;
            const uint4* src = bbase + (size_t)(ntb + nt_l) * KTP_total * 32 + rem;
            cpa16(sb + i * 16, src);
        }
        CP_COMMIT();
    }
    if (tid < 32) toks[tid] = gather ? tokptr[tid * tokstride] : 0;
    __syncthreads();
    MMA_STAGE_A(8, 256)
    CP_WAIT0();
    __syncthreads();

    const int ntbase = ntb + warp * 4;
    float acc[4][2][4];
#pragma unroll
    for (int q = 0; q < 4; q++)
#pragma unroll
        for (int mt = 0; mt < 2; mt++)
#pragma unroll
            for (int u = 0; u < 4; u++) acc[q][mt][u] = 0.f;

    const int BSTRIDE = 4 * 32;   // per-nt stride in uint4
#pragma unroll
    for (int ktp = 0; ktp < 4; ktp++) {
        MMA_CONSUME_KTP(ktp, (warp * 4) * BSTRIDE + ktp * 32)
    }

    float* Co = g_gp + (size_t)blockIdx.y * BB * G4;
    MMA_WRITE_PART(4, Co, G4)

    __threadfence();
    __syncthreads();
    if (tid == 0) s_last = atomicAdd(&cnt[t * 16 + blockIdx.x], 1);
    __syncthreads();
    if (s_last != S - 1) return;
    __threadfence();

    const int bx = blockIdx.x;
    for (int it = tid; it < 2048; it += 256) {
        int row = it >> 6, uu = it & 63;
        int P = 2 * bx + (uu >> 5), u = uu & 31;
        int base = (P << 7) + u;
        int d = (P << 5) + u;
        float ig = bias[d], fg = bias[d + DH], gg = bias[d + 2 * DH], og = bias[d + 3 * DH];
        for (int s = 0; s < S; s++) {
            const float* gp = g_gp + (size_t)s * BB * G4 + (size_t)row * G4 + base;
            ig += gp[0]; fg += gp[32]; gg += gp[64]; og += gp[96];
        }
        int hi_ = row * DH + d;
        float c = g_c[hi_];
        c = sigm(fg) * c + sigm(ig) * tanhf(gg);
        float h = sigm(og) * tanhf(c);
        g_c[hi_] = c;
        g_h[hi_] = h;
        if (store_enc) g_eo2[((size_t)row * LL + t) * DH + d] = h;
    }
}

// =========================================================================
// comb GEMM + fused bias/ReLU. grid = (4, 16), 256 thr. Same staging.
// =========================================================================
__global__ void __launch_bounds__(256) k_comb_mma(
    const uint4* __restrict__ Bfrag4, int KTP_total,
    const float* __restrict__ srcA0, const float* __restrict__ srcA1, int bnd,
    const int* __restrict__ tokptr,
    const float* __restrict__ bias, int t, int* __restrict__ cnt)
{
    extern __shared__ __align__(16) char dsm[];
    uint4* Bs4 = reinterpret_cast<uint4*>(dsm);
    unsigned* Af = reinterpret_cast<unsigned*>(dsm + 65536);
    __shared__ int toks[32];
    __shared__ int s_last;
    const int tid = threadIdx.x, lane = tid & 31, warp = tid >> 5;
    const int ktp0 = blockIdx.y * 4;
    const int c0 = ktp0 * 32;
    const int ntb = blockIdx.x * 32;
    const int gather = 1;

    {
        unsigned sb = sptr(Bs4);
        const uint4* bbase = Bfrag4 + (size_t)ktp0 * 32;
        for (int i = tid; i < 4096; i += 256) {
            int nt_l = i >> 7, rem = i & 127;
            const uint4* src = bbase + (size_t)(ntb + nt_l) * KTP_total * 32 + rem;
            cpa16(sb + i * 16, src);
        }
        CP_COMMIT();
    }
    if (tid < 32) toks[tid] = tokptr[tid];
    __syncthreads();
    MMA_STAGE_A(8, 256)
    CP_WAIT0();
    __syncthreads();

    const int ntbase = ntb + warp * 4;
    float acc[4][2][4];
#pragma unroll
    for (int q = 0; q < 4; q++)
#pragma unroll
        for (int mt = 0; mt < 2; mt++)
#pragma unroll
            for (int u = 0; u < 4; u++) acc[q][mt][u] = 0.f;

    const int BSTRIDE = 4 * 32;
#pragma unroll
    for (int ktp = 0; ktp < 4; ktp++) {
        MMA_CONSUME_KTP(ktp, (warp * 4) * BSTRIDE + ktp * 32)
    }

    float* Co = g_cpp + (size_t)blockIdx.y * BB * DH;
    MMA_WRITE_PART(4, Co, DH)

    __threadfence();
    __syncthreads();
    if (tid == 0) s_last = atomicAdd(&cnt[t * 4 + blockIdx.x], 1);
    __syncthreads();
    if (s_last != 15) return;
    __threadfence();

    for (int it = tid; it < 8192; it += 256) {
        int row = it >> 8, jj = it & 255;
        int j = blockIdx.x * 256 + jj;
        float s = bias[j];
#pragma unroll
        for (int u = 0; u < 16; u++)
            s += g_cpp[(size_t)u * BB * DH + (size_t)row * DH + j];
        g_inp[row * DH + j] = fmaxf(s, 0.f);
    }
}

// =========================================================================
// out projection: k-split 2, chunked double-buffered B (32KB x2),
// last-arrival fused finalize. grid = (125, 2), 256 thr.
// =========================================================================
__global__ void __launch_bounds__(256) k_outproj_mma(
    const uint4* __restrict__ Bfrag4,
    const float* __restrict__ out_b, float* __restrict__ out, int t,
    int* __restrict__ cnt)
{
    extern __shared__ __align__(16) char dsm[];
    uint4* Bs4 = reinterpret_cast<uint4*>(dsm);              // 2 x 2048 uint4 = 64KB
    unsigned* Af = reinterpret_cast<unsigned*>(dsm + 65536); // 32KB (reused as vals)
    __shared__ int s_last;
    const int tid = threadIdx.x, lane = tid & 31, warp = tid >> 5;
    const int KTP_total = 32;
    const int ktp0s = blockIdx.y * 16;     // 16 ktp per k-half
    const int c0 = blockIdx.y * 512;
    const int ntb = blockIdx.x * 32;
    unsigned sb = sptr(Bs4);

    // stage chunks 0 and 1
#pragma unroll
    for (int ch = 0; ch < 2; ch++) {
        const uint4* bbase = Bfrag4 + (size_t)(ktp0s + ch * 2) * 32;
        for (int i = tid; i < 2048; i += 256) {
            int nt_l = i >> 6, rem = i & 63;
            const uint4* src = bbase + (size_t)(ntb + nt_l) * KTP_total * 32 + rem;
            cpa16(sb + (ch * 2048 + i) * 16, src);
        }
        CP_COMMIT();
    }

    // stage A (32 kt) for this k-half
    for (int i = tid; i < 32 * 256; i += 256) {
        int r = i & 3, ln = (i >> 2) & 31, mt = (i >> 7) & 1, kt = i >> 8;
        int gg_ = ln >> 2, tg_ = ln & 3;
        int row = mt * 16 + gg_ + ((r & 1) << 3);
        int colG = c0 + kt * 16 + tg_ * 2 + ((r >> 1) << 3);
        float2 v = *reinterpret_cast<const float2*>(g_h + (size_t)row * DH + colG);
        Af[i] = packbf(v.x, v.y);
    }

    const int ntbase = ntb + warp * 4;
    float acc[4][2][4];
#pragma unroll
    for (int q = 0; q < 4; q++)
#pragma unroll
        for (int mt = 0; mt < 2; mt++)
#pragma unroll
            for (int u = 0; u < 4; u++) acc[q][mt][u] = 0.f;

    __syncthreads();   // A visible to all warps

    const int BSTRIDE = 2 * 32;   // per-nt stride within one buffer
#pragma unroll 1
    for (int ch = 0; ch < 8; ch++) {
        if (ch == 7) { CP_WAIT0(); } else { CP_WAIT1(); }
        __syncthreads();
        int bufb = (ch & 1) * 2048;
#pragma unroll
        for (int kl = 0; kl < 2; kl++) {
            MMA_CONSUME_KTP(ch * 2 + kl, bufb + (warp * 4) * BSTRIDE + kl * 32)
        }
        __syncthreads();
        if (ch + 2 < 8) {
            const uint4* bbase = Bfrag4 + (size_t)(ktp0s + (ch + 2) * 2) * 32;
            for (int i = tid; i < 2048; i += 256) {
                int nt_l = i >> 6, rem = i & 63;
                const uint4* src = bbase + (size_t)(ntb + nt_l) * KTP_total * 32 + rem;
                cpa16(sb + (bufb + i) * 16, src);
            }
            CP_COMMIT();
        }
    }

    // write my k-half partial
    float* Co = g_lg + (size_t)blockIdx.y * BB * VV;
    MMA_WRITE_PART(4, Co, VV)

    __threadfence();
    __syncthreads();
    if (tid == 0) s_last = atomicAdd(&cnt[t * NPO + blockIdx.x], 1);
    __syncthreads();
    if (s_last != 1) return;
    __threadfence();

    // finalize: vals = own acc + other half partial + bias; store raw logits
    const float* other = g_lg + (size_t)(1 - blockIdx.y) * BB * VV;
    float (*vals)[256] = reinterpret_cast<float (*)[256]>(Af);
    __syncthreads();
    {
        int gg_ = lane >> 2, tg_ = lane & 3;
#pragma unroll
        for (int q = 0; q < 4; q++) {
            int ncol = (ntbase + q) * 8 + tg_ * 2;
            int lcol = (warp * 4 + q) * 8 + tg_ * 2;
#pragma unroll
            for (int mt = 0; mt < 2; mt++) {
#pragma unroll
                for (int half = 0; half < 2; half++) {
                    int row = mt * 16 + gg_ + half * 8;
#pragma unroll
                    for (int cc = 0; cc < 2; cc++) {
                        float v = acc[q][mt][half * 2 + cc]
                                + other[(size_t)row * VV + ncol + cc]
                                + out_b[ncol + cc];
                        out[((size_t)row * LL + t) * VV + ncol + cc] = v;
                        vals[row][lcol + cc] = v;
                    }
                }
            }
        }
    }
    __syncthreads();

#pragma unroll
    for (int r4 = 0; r4 < 4; r4++) {
        int row = warp * 4 + r4;
        float s = 0.f, m = -1e30f;
        int mi = 0x7fffffff;
#pragma unroll
        for (int k = 0; k < 8; k++) {
            int c = lane + 32 * k;
            float v = vals[row][c];
            s += expf(v);
            if (v > m) { m = v; mi = blockIdx.x * 256 + c; }
        }
#pragma unroll
        for (int o = 16; o; o >>= 1) {
            s += __shfl_down_sync(0xffffffffu, s, o);
            float om = __shfl_down_sync(0xffffffffu, m, o);
            int   oi = __shfl_down_sync(0xffffffffu, mi, o);
            if (om > m || (om == m && oi < mi)) { m = om; mi = oi; }
        }
        if (lane == 0) {
            g_psum[row * NPO + blockIdx.x] = s;
            g_pmax[row * NPO + blockIdx.x] = m;
            g_pidx[row * NPO + blockIdx.x] = mi;
        }
    }
}

// =========================================================================
// Fused attention
// =========================================================================
__global__ void __launch_bounds__(256) k_attn(
    const float* __restrict__ dec_embed,
    const float* __restrict__ attn_b)
{
    __shared__ float cat_s[2 * DH];
    __shared__ float sp[4][LL];
    __shared__ float sc[LL], exs[LL], aw[LL];
    const int b = blockIdx.x, tid = threadIdx.x;
    const int tok = g_tok[b];

    for (int i = tid; i < DH; i += 256) {
        cat_s[i] = dec_embed[(size_t)tok * DH + i];
        cat_s[DH + i] = g_h[b * DH + i];
    }
    __syncthreads();
    {
        int l = tid & 63, kc = tid >> 6;
        int k0 = kc * 512;
        const float4* wp = reinterpret_cast<const float4*>(g_attnT + (size_t)l * 2048 + k0);
        const float4* cp = reinterpret_cast<const float4*>(cat_s + k0);
        float s = 0.f;
#pragma unroll 8
        for (int j = 0; j < 128; j++) {
            float4 w = wp[j];
            float4 c = cp[j];
            s += w.x * c.x + w.y * c.y + w.z * c.z + w.w * c.w;
        }
        sp[kc][l] = s;
    }
    __syncthreads();
    if (tid < LL)
        sc[tid] = attn_b[tid] + sp[0][tid] + sp[1][tid] + sp[2][tid] + sp[3][tid];
    __syncthreads();
    if (tid < LL) {
        float m = -1e30f;
        for (int i = 0; i < LL; i++) m = fmaxf(m, sc[i]);
        exs[tid] = expf(sc[tid] - m);
    }
    __syncthreads();
    if (tid < LL) {
        float tot = 0.f;
        for (int i = 0; i < LL; i++) tot += exs[i];
        aw[tid] = exs[tid] / tot;
    }
    __syncthreads();
    {
        int d0 = tid * 4;
        float4 a4 = make_float4(0.f, 0.f, 0.f, 0.f);
        const float4* ep = reinterpret_cast<const float4*>(g_eo2 + (size_t)b * LL * DH + d0);
#pragma unroll 8
        for (int l = 0; l < LL; l++) {
            float w = aw[l];
            float4 e = ep[(size_t)l * (DH / 4)];
            a4.x += w * e.x; a4.y += w * e.y; a4.z += w * e.z; a4.w += w * e.w;
        }
        *reinterpret_cast<float4*>(g_ctx + b * DH + d0) = a4;
    }
}

// ---------------- reduce 125 partials -> lse + token ----------------
__global__ void k_reduce(int t) {
    __shared__ float ss[128], sm[128];
    __shared__ int   si[128];
    int b = blockIdx.x, tid = threadIdx.x;
    float s = 0.f, m = -1e30f;
    int mi = 0x7fffffff;
    for (int i = tid; i < NPO; i += 128) {
        s += g_psum[b * NPO + i];
        float om = g_pmax[b * NPO + i];
        int oi = g_pidx[b * NPO + i];
        if (om > m || (om == m && oi < mi)) { m = om; mi = oi; }
    }
    ss[tid] = s; sm[tid] = m; si[tid] = mi;
    __syncthreads();
    for (int o = 64; o; o >>= 1) {
        if (tid < o) {
            ss[tid] += ss[tid + o];
            if (sm[tid + o] > sm[tid] ||
                (sm[tid + o] == sm[tid] && si[tid + o] < si[tid])) {
                sm[tid] = sm[tid + o];
                si[tid] = si[tid + o];
            }
        }
        __syncthreads();
    }
    if (tid == 0) {
        g_lse[t * BB + b] = logf(ss[0]);
        g_tok[b] = si[0];
    }
}

// ---------------- final pass: out -= lse ----------------
__global__ void k_finalize(float* __restrict__ out) {
    long idx = (long)blockIdx.x * blockDim.x + threadIdx.x;
    if (idx < (long)BB * LL * VV) {
        long r = idx / VV;
        int t = (int)(r % LL);
        int b = (int)(r / LL);
        out[idx] -= g_lse[t * BB + b];
    }
}

// ---------------- host orchestration ----------------
extern "C" void kernel_launch(void* const* d_in, const int* in_sizes, int n_in,
                              void* d_out, int out_size) {
    const int*   x         = (const int*)  d_in[0];
    const float* enc_embed = (const float*)d_in[1];
    const float* enc_wx    = (const float*)d_in[2];
    const float* enc_wh    = (const float*)d_in[3];
    const float* enc_b     = (const float*)d_in[4];
    const float* dec_embed = (const float*)d_in[5];
    const float* attn_w    = (const float*)d_in[6];
    const float* attn_b    = (const float*)d_in[7];
    const float* comb_w    = (const float*)d_in[8];
    const float* comb_b    = (const float*)d_in[9];
    const float* dec_wx    = (const float*)d_in[10];
    const float* dec_wh    = (const float*)d_in[11];
    const float* dec_b     = (const float*)d_in[12];
    const float* out_w     = (const float*)d_in[13];
    const float* out_b     = (const float*)d_in[14];
    float* out = (float*)d_out;

    uint4 *pBout, *pBdec, *pBenc, *pBcomb;
    float *p_h, *p_inp, *p_ctx;
    int *p_tok, *p_ce, *p_cd, *p_cc, *p_co;
    cudaGetSymbolAddress((void**)&pBout, Bout4);
    cudaGetSymbolAddress((void**)&pBdec, Bdec4);
    cudaGetSymbolAddress((void**)&pBenc, Benc4);
    cudaGetSymbolAddress((void**)&pBcomb, Bcomb4);
    cudaGetSymbolAddress((void**)&p_h, g_h);
    cudaGetSymbolAddress((void**)&p_inp, g_inp);
    cudaGetSymbolAddress((void**)&p_ctx, g_ctx);
    cudaGetSymbolAddress((void**)&p_tok, g_tok);
    cudaGetSymbolAddress((void**)&p_ce, g_cnt_enc);
    cudaGetSymbolAddress((void**)&p_cd, g_cnt_dec);
    cudaGetSymbolAddress((void**)&p_cc, g_cnt_comb);
    cudaGetSymbolAddress((void**)&p_co, g_cnt_out);

    cudaFuncSetAttribute(k_gates_mma, cudaFuncAttributeMaxDynamicSharedMemorySize, 73728);
    cudaFuncSetAttribute(k_comb_mma, cudaFuncAttributeMaxDynamicSharedMemorySize, 73728);
    cudaFuncSetAttribute(k_outproj_mma, cudaFuncAttributeMaxDynamicSharedMemorySize, 98304);

    // launches 1..3 before the hot gates class (ncu -s alignment)
    k_init<<<128, 256>>>(0);
    k_prepB4<<<3072, 256>>>(enc_wx, enc_wh, 512, G4, 48, 512, 1, pBenc);
    k_prepB4<<<1024, 256>>>(comb_w, comb_w, 2048, DH, 64, 128, 0, pBcomb);

    // ---------- encoder: 12 K-slices ----------
    for (int t = 0; t < LL; t++) {
        k_gates_mma<<<dim3(16, 12), 256, 73728>>>(pBenc, 48, enc_embed, p_h, 512,
                                                  1, x + t, LL, enc_b, 12, t, 1, p_ce);
    }

    k_prepB4<<<16000, 256>>>(out_w, out_w, 1024, VV, 32, 4000, 0, pBout);
    k_prepB4<<<4096, 256>>>(dec_wx, dec_wh, 1024, G4, 64, 512, 1, pBdec);
    k_prepAttnT<<<512, 256>>>(attn_w);

    // ---------- decoder ----------
    k_init<<<128, 256>>>(1);
    for (int t = 0; t < LL; t++) {
        k_attn<<<BB, 256>>>(dec_embed, attn_b);
        k_comb_mma<<<dim3(4, 16), 256, 73728>>>(pBcomb, 64, dec_embed, p_ctx, 1024,
                                                p_tok, comb_b, t, p_cc);
        k_gates_mma<<<dim3(16, 16), 256, 73728>>>(pBdec, 64, p_inp, p_h, 1024,
                                                  0, p_tok, 1, dec_b, 16, t, 0, p_cd);
        k_outproj_mma<<<dim3(NPO, 2), 256, 98304>>>(pBout, out_b, out, t, p_co);
        k_reduce<<<BB, 128>>>(t);
    }

    long total = (long)BB * LL * VV;
    k_finalize<<<(int)((total + 255) / 256), 256>>>(out);
}